// round 11
// baseline (speedup 1.0000x reference)
#include <cuda_runtime.h>
#include <cuda_bf16.h>
#include <cuda_fp16.h>
#include <cstdint>
#include <math.h>

#define NB 4
#define NS 2048
#define NHID 1024
#define NHEADS 16
#define DHEAD 64
#define MTOT (NB * NS)   // 8192

// ---------------------------------------------------------------------------
// Global scratch
// ---------------------------------------------------------------------------
__device__ __nv_bfloat16 g_xh[MTOT * NHID], g_xl[MTOT * NHID];
__device__ __nv_bfloat16 g_wh[3 * NHID * NHID], g_wl[3 * NHID * NHID];   // Wq|Wk|Wv
__device__ __nv_bfloat16 g_woh[NHID * NHID], g_wol[NHID * NHID];
__device__ __nv_bfloat16 g_qh[NB * NHEADS * NS * DHEAD], g_ql[NB * NHEADS * NS * DHEAD];
__device__ __nv_bfloat16 g_kh[NB * NHEADS * NS * DHEAD], g_kl[NB * NHEADS * NS * DHEAD];
__device__ __half        g_vh[NB * NHEADS * NS * DHEAD];   // single fp16 V
__device__ __nv_bfloat16 g_ah[MTOT * NHID], g_al[MTOT * NHID];

// ===========================================================================
// Helpers
// ===========================================================================
__device__ __forceinline__ uint32_t smem_to_u32(const void* p) {
    uint32_t a;
    asm("{ .reg .u64 t; cvta.to.shared.u64 t, %1; cvt.u32.u64 %0, t; }"
        : "=r"(a) : "l"(p));
    return a;
}
__device__ __forceinline__ void cp_async16(uint32_t s, const void* g) {
    asm volatile("cp.async.cg.shared.global [%0], [%1], 16;" :: "r"(s), "l"(g));
}
__device__ __forceinline__ void cp_commit() {
    asm volatile("cp.async.commit_group;" ::: "memory");
}
template <int N>
__device__ __forceinline__ void cp_wait() {
    asm volatile("cp.async.wait_group %0;" :: "n"(N) : "memory");
}
__device__ __forceinline__ void ldmatrix_x4(uint32_t& d0, uint32_t& d1,
                                            uint32_t& d2, uint32_t& d3,
                                            uint32_t addr) {
    asm volatile("ldmatrix.sync.aligned.m8n8.x4.shared.b16 {%0,%1,%2,%3}, [%4];"
        : "=r"(d0), "=r"(d1), "=r"(d2), "=r"(d3) : "r"(addr));
}
__device__ __forceinline__ void ldmatrix_x4_trans(uint32_t& d0, uint32_t& d1,
                                                  uint32_t& d2, uint32_t& d3,
                                                  uint32_t addr) {
    asm volatile("ldmatrix.sync.aligned.m8n8.x4.trans.shared.b16 {%0,%1,%2,%3}, [%4];"
        : "=r"(d0), "=r"(d1), "=r"(d2), "=r"(d3) : "r"(addr));
}
__device__ __forceinline__ void mma_bf16(float* c, const uint32_t* a,
                                         const uint32_t* b) {
    asm volatile(
        "mma.sync.aligned.m16n8k16.row.col.f32.bf16.bf16.f32 "
        "{%0,%1,%2,%3}, {%4,%5,%6,%7}, {%8,%9}, {%0,%1,%2,%3};"
        : "+f"(c[0]), "+f"(c[1]), "+f"(c[2]), "+f"(c[3])
        : "r"(a[0]), "r"(a[1]), "r"(a[2]), "r"(a[3]), "r"(b[0]), "r"(b[1]));
}
__device__ __forceinline__ void mma_f16(float* c, const uint32_t* a,
                                        const uint32_t* b) {
    asm volatile(
        "mma.sync.aligned.m16n8k16.row.col.f32.f16.f16.f32 "
        "{%0,%1,%2,%3}, {%4,%5,%6,%7}, {%8,%9}, {%0,%1,%2,%3};"
        : "+f"(c[0]), "+f"(c[1]), "+f"(c[2]), "+f"(c[3])
        : "r"(a[0]), "r"(a[1]), "r"(a[2]), "r"(a[3]), "r"(b[0]), "r"(b[1]));
}
__device__ __forceinline__ uint32_t packbf(__nv_bfloat16 x, __nv_bfloat16 y) {
    __nv_bfloat162 p; p.x = x; p.y = y;
    return *reinterpret_cast<uint32_t*>(&p);
}
__device__ __forceinline__ void split2(float x, float y,
                                       uint32_t& hi, uint32_t& lo) {
    __nv_bfloat16 hx = __float2bfloat16_rn(x);
    __nv_bfloat16 hy = __float2bfloat16_rn(y);
    hi = packbf(hx, hy);
    lo = packbf(__float2bfloat16_rn(x - __bfloat162float(hx)),
                __float2bfloat16_rn(y - __bfloat162float(hy)));
}
__device__ __forceinline__ void split4(float4 v, uint2& hi, uint2& lo) {
    split2(v.x, v.y, hi.x, lo.x);
    split2(v.z, v.w, hi.y, lo.y);
}
__device__ __forceinline__ uint32_t f2h2(float x, float y) {
    uint32_t r;
    asm("cvt.rn.f16x2.f32 %0, %1, %2;" : "=r"(r) : "f"(y), "f"(x));
    return r;
}
__device__ __forceinline__ float ex2f(float x) {
    float r;
    asm("ex2.approx.f32 %0, %1;" : "=f"(r) : "f"(x));
    return r;
}
__device__ __forceinline__ uint32_t ex2h2(uint32_t x) {
    uint32_t r;
    asm("ex2.approx.f16x2 %0, %1;" : "=r"(r) : "r"(x));
    return r;
}

#define L2E 1.4426950408889634f

// ===========================================================================
// Split kernel: fp32 -> bf16 hi/lo
// ===========================================================================
__global__ __launch_bounds__(256)
void split_kernel(const float* __restrict__ src,
                  __nv_bfloat16* __restrict__ h,
                  __nv_bfloat16* __restrict__ l, int n4)
{
    int i = blockIdx.x * 256 + threadIdx.x;
    if (i < n4) {
        float4 v = ((const float4*)src)[i];
        uint2 hi, lo;
        split4(v, hi, lo);
        ((uint2*)h)[i] = hi;
        ((uint2*)l)[i] = lo;
    }
}

// ===========================================================================
// All-bf16 cp.async GEMM: CTA 128x256, warp 64x64, BK=32, 3 stages. (unchanged)
// ===========================================================================
#define GLDS 40
#define GA_BUF 10240
#define GB_BUF 20480
#define GSTAGE (2 * GA_BUF + 2 * GB_BUF)
#define GEMM_SMEM (3 * GSTAGE)

__global__ __launch_bounds__(256, 1)
void gemm_bf16_kernel(const __nv_bfloat16* __restrict__ Ah,
                      const __nv_bfloat16* __restrict__ Al,
                      const __nv_bfloat16* __restrict__ Bh,
                      const __nv_bfloat16* __restrict__ Bl,
                      float* __restrict__ Cf, int qkvMode)
{
    extern __shared__ char smc[];
    const uint32_t sb = smem_to_u32(smc);

    const int t    = threadIdx.x;
    const int lane = t & 31;
    const int wid  = t >> 5;
    const int wm   = wid & 1;
    const int wn   = wid >> 1;
    const int m0   = blockIdx.y << 7;
    const int n0   = blockIdx.x << 8;

    const int rA = lane & 15;
    const int cA = (lane >> 4) << 3;
    const int rB = (lane & 7) + ((lane >> 4) << 3);
    const int cB = lane & 8;

    auto issue = [&](int c, int stg) {
        const int k0 = c << 5;
        const uint32_t st = sb + stg * GSTAGE;
#pragma unroll
        for (int j = 0; j < 2; j++) {
            int idx = t + (j << 8);
            int row = idx >> 2, ch = idx & 3;
            uint32_t so = (uint32_t)(row * 80 + ch * 16);
            const size_t go = (size_t)(m0 + row) * NHID + k0 + ch * 8;
            cp_async16(st + so, Ah + go);
            cp_async16(st + GA_BUF + so, Al + go);
        }
#pragma unroll
        for (int j = 0; j < 4; j++) {
            int idx = t + (j << 8);
            int row = idx >> 2, ch = idx & 3;
            uint32_t so = (uint32_t)(row * 80 + ch * 16);
            const size_t go = (size_t)(n0 + row) * NHID + k0 + ch * 8;
            cp_async16(st + 2 * GA_BUF + so, Bh + go);
            cp_async16(st + 2 * GA_BUF + GB_BUF + so, Bl + go);
        }
        cp_commit();
    };

    float acc[4][8][4];
#pragma unroll
    for (int mf = 0; mf < 4; mf++)
#pragma unroll
        for (int nf = 0; nf < 8; nf++)
#pragma unroll
            for (int r = 0; r < 4; r++) acc[mf][nf][r] = 0.f;

    issue(0, 0);
    issue(1, 1);

    for (int c = 0; c < 32; ++c) {
        if (c < 31) cp_wait<1>(); else cp_wait<0>();
        __syncthreads();
        if (c + 2 < 32) issue(c + 2, (c + 2) % 3);

        const uint32_t st = sb + (c % 3) * GSTAGE;
#pragma unroll
        for (int ks = 0; ks < 2; ks++) {
            const int k0 = ks << 4;
            uint32_t ah[4][4], al[4][4];
#pragma unroll
            for (int mf = 0; mf < 4; mf++) {
                uint32_t ro = (uint32_t)((wm * 64 + mf * 16 + rA) * GLDS + k0 + cA) * 2;
                ldmatrix_x4(ah[mf][0], ah[mf][1], ah[mf][2], ah[mf][3], st + ro);
                ldmatrix_x4(al[mf][0], al[mf][1], al[mf][2], al[mf][3], st + GA_BUF + ro);
            }
#pragma unroll
            for (int p = 0; p < 4; p++) {
                uint32_t ro = (uint32_t)((wn * 64 + p * 16 + rB) * GLDS + k0 + cB) * 2;
                uint32_t h0, h1, h2, h3, e0, e1, e2, e3;
                ldmatrix_x4(h0, h1, h2, h3, st + 2 * GA_BUF + ro);
                ldmatrix_x4(e0, e1, e2, e3, st + 2 * GA_BUF + GB_BUF + ro);
                uint32_t bh0[2] = {h0, h1}, bh1[2] = {h2, h3};
                uint32_t bl0[2] = {e0, e1}, bl1[2] = {e2, e3};
#pragma unroll
                for (int mf = 0; mf < 4; mf++) {
                    mma_bf16(acc[mf][2 * p],     ah[mf], bh0);
                    mma_bf16(acc[mf][2 * p],     ah[mf], bl0);
                    mma_bf16(acc[mf][2 * p],     al[mf], bh0);
                    mma_bf16(acc[mf][2 * p + 1], ah[mf], bh1);
                    mma_bf16(acc[mf][2 * p + 1], ah[mf], bl1);
                    mma_bf16(acc[mf][2 * p + 1], al[mf], bh1);
                }
            }
        }
    }

    const int rowBase = m0 + wm * 64 + (lane >> 2);
    const int colBase = n0 + wn * 64 + ((lane & 3) << 1);

    if (qkvMode) {
        const int which = n0 >> 10;
        const float sc = (which == 0) ? 0.125f * L2E : 1.0f;
#pragma unroll
        for (int mf = 0; mf < 4; mf++)
#pragma unroll
            for (int nf = 0; nf < 8; nf++) {
                int n = colBase + nf * 8;
                int r = n & 1023;
                int h = r >> 6, d = r & 63;
#pragma unroll
                for (int half = 0; half < 2; half++) {
                    int m = rowBase + mf * 16 + half * 8;
                    int b = m >> 11, s = m & (NS - 1);
                    size_t idx = ((((size_t)(b * NHEADS + h)) * NS + s) << 6) + d;
                    if (which == 2) {
                        *(uint32_t*)(g_vh + idx) =
                            f2h2(acc[mf][nf][half * 2], acc[mf][nf][half * 2 + 1]);
                    } else {
                        uint32_t hi, lo;
                        split2(acc[mf][nf][half * 2] * sc,
                               acc[mf][nf][half * 2 + 1] * sc, hi, lo);
                        if (which == 0) {
                            *(uint32_t*)(g_qh + idx) = hi;
                            *(uint32_t*)(g_ql + idx) = lo;
                        } else {
                            *(uint32_t*)(g_kh + idx) = hi;
                            *(uint32_t*)(g_kl + idx) = lo;
                        }
                    }
                }
            }
    } else {
#pragma unroll
        for (int mf = 0; mf < 4; mf++)
#pragma unroll
            for (int nf = 0; nf < 8; nf++) {
                int n = colBase + nf * 8;
#pragma unroll
                for (int half = 0; half < 2; half++) {
                    int m = rowBase + mf * 16 + half * 8;
                    *(float2*)(Cf + (size_t)m * NHID + n) =
                        make_float2(acc[mf][nf][half * 2], acc[mf][nf][half * 2 + 1]);
                }
            }
    }
}

// ===========================================================================
// Flash attention v3: CTA = 256 q-rows, K-tile 64, 8 warps x 32 q-rows (2 mf).
// K/V fragments loaded once per warp, reused by both m-halves.
// QK bf16 3-term (log2 domain); exp computed INLINE in PV loop via
// ex2.approx.f16x2 (no pp array -> register-disciplined); V single fp16;
// row-sum l via ones-MMA.
// ===========================================================================
#define KT 64
#define QT 256
#define ALDS 72
#define AQBUF (QT * 144)           // 36864 per Q buffer
#define AKBUF (KT * 144)           // 9216 per K/V buffer
#define ASTG (3 * AKBUF)           // Kh, Kl, Vh = 27648
#define OQH 0
#define OQL AQBUF
#define OST (2 * AQBUF)            // 73728
#define OMSK (OST + 2 * ASTG)      // 129024
#define ATTN_SMEM (OMSK + 1024)

__global__ __launch_bounds__(256, 1)
void attn_tc_kernel(const float* __restrict__ mask)
{
    extern __shared__ char smc[];
    const uint32_t sb = smem_to_u32(smc);

    const int t    = threadIdx.x;
    const int lane = t & 31;
    const int w    = t >> 5;

    const int bh = blockIdx.y;
    const int b  = bh >> 4;
    const int h  = bh & 15;
    const int q0 = blockIdx.x << 8;

    const int rA = lane & 15;
    const int cA = (lane >> 4) << 3;
    const int rB = (lane & 7) + ((lane >> 4) << 3);
    const int cB = lane & 8;
    const int c0 = (lane & 3) << 1;

    const size_t qbase  = ((size_t)bh * NS + q0) * DHEAD;
    const size_t kvbase = (size_t)bh * NS * DHEAD;

    auto issue_kv = [&](int kt, int stg) {
        const size_t base = kvbase + (size_t)kt * KT * DHEAD;
        const uint32_t st = sb + OST + stg * ASTG;
#pragma unroll
        for (int j = 0; j < 2; j++) {            // 64 rows x 8 chunks
            int idx = t + (j << 8);
            int row = idx >> 3, ch = idx & 7;
            uint32_t so = (uint32_t)(row * 144 + ch * 16);
            size_t go = base + row * DHEAD + ch * 8;
            cp_async16(st + 0 * AKBUF + so, g_kh + go);
            cp_async16(st + 1 * AKBUF + so, g_kl + go);
            cp_async16(st + 2 * AKBUF + so, g_vh + go);
        }
        if (t < 16)
            cp_async16(sb + OMSK + stg * 512 + t * 16,
                       mask + (size_t)b * NS + kt * KT + t * 4);
        cp_commit();
    };

    // prologue: Q tile (256x64, hi/lo) + KV stage 0
#pragma unroll
    for (int j = 0; j < 8; j++) {
        int idx = t + (j << 8);
        int row = idx >> 3, ch = idx & 7;
        uint32_t so = (uint32_t)(row * 144 + ch * 16);
        size_t go = qbase + row * DHEAD + ch * 8;
        cp_async16(sb + OQH + so, g_qh + go);
        cp_async16(sb + OQL + so, g_ql + go);
    }
    issue_kv(0, 0);

    float accs[2][8][4];       // raw (masked) scores per mf
    float acco[2][8][4];
    float accl[2][4];
    float mrow[2][2];
#pragma unroll
    for (int mf = 0; mf < 2; mf++) {
        mrow[mf][0] = -INFINITY; mrow[mf][1] = -INFINITY;
#pragma unroll
        for (int r = 0; r < 4; r++) accl[mf][r] = 0.f;
#pragma unroll
        for (int nf = 0; nf < 8; nf++)
#pragma unroll
            for (int r = 0; r < 4; r++) acco[mf][nf][r] = 0.f;
    }

    const uint32_t bones[2] = {0x3C003C00u, 0x3C003C00u};  // fp16 ones

    for (int kt = 0; kt < NS / KT; kt++) {
        cp_wait<0>();
        __syncthreads();
        if (kt + 1 < NS / KT) issue_kv(kt + 1, (kt + 1) & 1);

        const int stg = kt & 1;
        const uint32_t st = sb + OST + stg * ASTG;
        const float* msk = (const float*)(smc + OMSK + stg * 512);

        // ---- S = Q K^T : K frags loaded once, used by both m-halves ----
#pragma unroll
        for (int mf = 0; mf < 2; mf++)
#pragma unroll
            for (int nf = 0; nf < 8; nf++)
#pragma unroll
                for (int r = 0; r < 4; r++) accs[mf][nf][r] = 0.f;

#pragma unroll
        for (int ks = 0; ks < 4; ks++) {
            uint32_t aqh[2][4], aql[2][4];
#pragma unroll
            for (int mf = 0; mf < 2; mf++) {
                uint32_t qo = (uint32_t)((w * 32 + mf * 16 + rA) * ALDS + ks * 16 + cA) * 2;
                ldmatrix_x4(aqh[mf][0], aqh[mf][1], aqh[mf][2], aqh[mf][3], sb + OQH + qo);
                ldmatrix_x4(aql[mf][0], aql[mf][1], aql[mf][2], aql[mf][3], sb + OQL + qo);
            }
#pragma unroll
            for (int p = 0; p < 4; p++) {
                uint32_t ko = (uint32_t)((p * 16 + rB) * ALDS + ks * 16 + cB) * 2;
                uint32_t h0, h1, h2, h3, e0, e1, e2, e3;
                ldmatrix_x4(h0, h1, h2, h3, st + 0 * AKBUF + ko);
                ldmatrix_x4(e0, e1, e2, e3, st + 1 * AKBUF + ko);
                uint32_t bhi0[2] = {h0, h1}, bhi1[2] = {h2, h3};
                uint32_t blo0[2] = {e0, e1}, blo1[2] = {e2, e3};
#pragma unroll
                for (int mf = 0; mf < 2; mf++) {
                    mma_bf16(accs[mf][2 * p],     aqh[mf], bhi0);
                    mma_bf16(accs[mf][2 * p],     aqh[mf], blo0);
                    mma_bf16(accs[mf][2 * p],     aql[mf], bhi0);
                    mma_bf16(accs[mf][2 * p + 1], aqh[mf], bhi1);
                    mma_bf16(accs[mf][2 * p + 1], aqh[mf], blo1);
                    mma_bf16(accs[mf][2 * p + 1], aql[mf], bhi1);
                }
            }
        }

        // ---- + mask*log2e, running max, O/l rescale (per mf) ----
#pragma unroll
        for (int mf = 0; mf < 2; mf++) {
#pragma unroll
            for (int nf = 0; nf < 8; nf++) {
                float mk0 = msk[nf * 8 + c0];
                float mk1 = msk[nf * 8 + c0 + 1];
                accs[mf][nf][0] = fmaf(mk0, L2E, accs[mf][nf][0]);
                accs[mf][nf][1] = fmaf(mk1, L2E, accs[mf][nf][1]);
                accs[mf][nf][2] = fmaf(mk0, L2E, accs[mf][nf][2]);
                accs[mf][nf][3] = fmaf(mk1, L2E, accs[mf][nf][3]);
            }
            float tm0 = -INFINITY, tm1 = -INFINITY;
#pragma unroll
            for (int nf = 0; nf < 8; nf++) {
                tm0 = fmaxf(tm0, fmaxf(accs[mf][nf][0], accs[mf][nf][1]));
                tm1 = fmaxf(tm1, fmaxf(accs[mf][nf][2], accs[mf][nf][3]));
            }
            tm0 = fmaxf(tm0, __shfl_xor_sync(0xffffffffu, tm0, 1));
            tm0 = fmaxf(tm0, __shfl_xor_sync(0xffffffffu, tm0, 2));
            tm1 = fmaxf(tm1, __shfl_xor_sync(0xffffffffu, tm1, 1));
            tm1 = fmaxf(tm1, __shfl_xor_sync(0xffffffffu, tm1, 2));

            float mn0 = fmaxf(mrow[mf][0], tm0);
            float mn1 = fmaxf(mrow[mf][1], tm1);
            float cr0 = ex2f(mrow[mf][0] - mn0);
            float cr1 = ex2f(mrow[mf][1] - mn1);
            mrow[mf][0] = mn0; mrow[mf][1] = mn1;

#pragma unroll
            for (int nf = 0; nf < 8; nf++) {
                acco[mf][nf][0] *= cr0; acco[mf][nf][1] *= cr0;
                acco[mf][nf][2] *= cr1; acco[mf][nf][3] *= cr1;
            }
            accl[mf][0] *= cr0;
            accl[mf][2] *= cr1;
        }

        // ---- O += P V : exp inline (f16x2), V frags shared by both mf ----
#pragma unroll
        for (int kc = 0; kc < 2; kc++) {
            uint32_t aph[2][4];
#pragma unroll
            for (int mf = 0; mf < 2; mf++) {
                aph[mf][0] = ex2h2(f2h2(accs[mf][2 * kc][0] - mrow[mf][0],
                                        accs[mf][2 * kc][1] - mrow[mf][0]));
                aph[mf][1] = ex2h2(f2h2(accs[mf][2 * kc][2] - mrow[mf][1],
                                        accs[mf][2 * kc][3] - mrow[mf][1]));
                aph[mf][2] = ex2h2(f2h2(accs[mf][2 * kc + 1][0] - mrow[mf][0],
                                        accs[mf][2 * kc + 1][1] - mrow[mf][0]));
                aph[mf][3] = ex2h2(f2h2(accs[mf][2 * kc + 1][2] - mrow[mf][1],
                                        accs[mf][2 * kc + 1][3] - mrow[mf][1]));
                mma_f16(accl[mf], aph[mf], bones);
            }
#pragma unroll
            for (int pv = 0; pv < 4; pv++) {
                uint32_t vo = (uint32_t)((kc * 16 + rA) * ALDS + pv * 16 + cA) * 2;
                uint32_t h0, h1, h2, h3;
                ldmatrix_x4_trans(h0, h1, h2, h3, st + 2 * AKBUF + vo);
                uint32_t bvh0[2] = {h0, h1}, bvh1[2] = {h2, h3};
#pragma unroll
                for (int mf = 0; mf < 2; mf++) {
                    mma_f16(acco[mf][2 * pv],     aph[mf], bvh0);
                    mma_f16(acco[mf][2 * pv + 1], aph[mf], bvh1);
                }
            }
        }
        // second half of K-tile (k rows 32..63 -> frag pairs 2,3)
#pragma unroll
        for (int kc = 2; kc < 4; kc++) {
            uint32_t aph[2][4];
#pragma unroll
            for (int mf = 0; mf < 2; mf++) {
                aph[mf][0] = ex2h2(f2h2(accs[mf][2 * kc][0] - mrow[mf][0],
                                        accs[mf][2 * kc][1] - mrow[mf][0]));
                aph[mf][1] = ex2h2(f2h2(accs[mf][2 * kc][2] - mrow[mf][1],
                                        accs[mf][2 * kc][3] - mrow[mf][1]));
                aph[mf][2] = ex2h2(f2h2(accs[mf][2 * kc + 1][0] - mrow[mf][0],
                                        accs[mf][2 * kc + 1][1] - mrow[mf][0]));
                aph[mf][3] = ex2h2(f2h2(accs[mf][2 * kc + 1][2] - mrow[mf][1],
                                        accs[mf][2 * kc + 1][3] - mrow[mf][1]));
                mma_f16(accl[mf], aph[mf], bones);
            }
#pragma unroll
            for (int pv = 0; pv < 4; pv++) {
                uint32_t vo = (uint32_t)((kc * 16 + rA) * ALDS + pv * 16 + cA) * 2;
                uint32_t h0, h1, h2, h3;
                ldmatrix_x4_trans(h0, h1, h2, h3, st + 2 * AKBUF + vo);
                uint32_t bvh0[2] = {h0, h1}, bvh1[2] = {h2, h3};
#pragma unroll
                for (int mf = 0; mf < 2; mf++) {
                    mma_f16(acco[mf][2 * pv],     aph[mf], bvh0);
                    mma_f16(acco[mf][2 * pv + 1], aph[mf], bvh1);
                }
            }
        }
    }

    // ---- epilogue ----
#pragma unroll
    for (int mf = 0; mf < 2; mf++) {
        float inv0 = 1.f / accl[mf][0];
        float inv1 = 1.f / accl[mf][2];
        int row0 = q0 + w * 32 + mf * 16 + (lane >> 2);
#pragma unroll
        for (int nf = 0; nf < 8; nf++) {
            int d = nf * 8 + c0;
            size_t i0 = ((size_t)(b * NS) + row0) * NHID + h * DHEAD + d;
            size_t i1 = i0 + (size_t)8 * NHID;
            uint32_t hi, lo;
            split2(acco[mf][nf][0] * inv0, acco[mf][nf][1] * inv0, hi, lo);
            *(uint32_t*)(g_ah + i0) = hi;
            *(uint32_t*)(g_al + i0) = lo;
            split2(acco[mf][nf][2] * inv1, acco[mf][nf][3] * inv1, hi, lo);
            *(uint32_t*)(g_ah + i1) = hi;
            *(uint32_t*)(g_al + i1) = lo;
        }
    }
}

// ---------------------------------------------------------------------------
// Launch
// ---------------------------------------------------------------------------
extern "C" void kernel_launch(void* const* d_in, const int* in_sizes, int n_in,
                              void* d_out, int out_size)
{
    const float* X    = (const float*)d_in[0];
    const float* mask = (const float*)d_in[1];
    const float* Wq   = (const float*)d_in[2];
    const float* Wk   = (const float*)d_in[3];
    const float* Wv   = (const float*)d_in[4];
    const float* Wo   = (const float*)d_in[5];
    float* out = (float*)d_out;

    __nv_bfloat16 *xh, *xl, *wh, *wl, *woh, *wol, *ah, *al;
    cudaGetSymbolAddress((void**)&xh, g_xh);   cudaGetSymbolAddress((void**)&xl, g_xl);
    cudaGetSymbolAddress((void**)&wh, g_wh);   cudaGetSymbolAddress((void**)&wl, g_wl);
    cudaGetSymbolAddress((void**)&woh, g_woh); cudaGetSymbolAddress((void**)&wol, g_wol);
    cudaGetSymbolAddress((void**)&ah, g_ah);   cudaGetSymbolAddress((void**)&al, g_al);

    cudaFuncSetAttribute(gemm_bf16_kernel,
                         cudaFuncAttributeMaxDynamicSharedMemorySize, GEMM_SMEM);
    cudaFuncSetAttribute(attn_tc_kernel,
                         cudaFuncAttributeMaxDynamicSharedMemorySize, ATTN_SMEM);

    int n4x = MTOT * NHID / 4;
    int n4w = NHID * NHID / 4;
    split_kernel<<<n4x / 256, 256>>>(X,  xh,  xl,  n4x);
    split_kernel<<<n4w / 256, 256>>>(Wq, wh,               wl,               n4w);
    split_kernel<<<n4w / 256, 256>>>(Wk, wh + NHID*NHID,   wl + NHID*NHID,   n4w);
    split_kernel<<<n4w / 256, 256>>>(Wv, wh + 2*NHID*NHID, wl + 2*NHID*NHID, n4w);
    split_kernel<<<n4w / 256, 256>>>(Wo, woh, wol, n4w);

    dim3 gq(3 * NHID / 256, MTOT / 128);   // 12 x 64
    gemm_bf16_kernel<<<gq, 256, GEMM_SMEM>>>(xh, xl, wh, wl, nullptr, 1);

    dim3 ga(NS / QT, NB * NHEADS);         // 8 x 64 = 512 CTAs
    attn_tc_kernel<<<ga, 256, ATTN_SMEM>>>(mask);

    dim3 go(NHID / 256, MTOT / 128);       // 4 x 64
    gemm_bf16_kernel<<<go, 256, GEMM_SMEM>>>(ah, al, woh, wol, out, 0);
}

// round 12
// speedup vs baseline: 1.1366x; 1.1366x over previous
#include <cuda_runtime.h>
#include <cuda_bf16.h>
#include <cuda_fp16.h>
#include <cstdint>
#include <math.h>

#define NB 4
#define NS 2048
#define NHID 1024
#define NHEADS 16
#define DHEAD 64
#define MTOT (NB * NS)   // 8192

// ---------------------------------------------------------------------------
// Global scratch
// ---------------------------------------------------------------------------
__device__ __half        g_x16[MTOT * NHID];                          // X single fp16
__device__ __half        g_wh16[3 * NHID * NHID], g_wl16[3 * NHID * NHID]; // Wq|Wk|Wv fp16 hi/lo
__device__ __nv_bfloat16 g_woh[NHID * NHID], g_wol[NHID * NHID];      // Wo bf16 hi/lo
__device__ __nv_bfloat16 g_qh[NB * NHEADS * NS * DHEAD], g_ql[NB * NHEADS * NS * DHEAD];
__device__ __nv_bfloat16 g_kh[NB * NHEADS * NS * DHEAD], g_kl[NB * NHEADS * NS * DHEAD];
__device__ __half        g_vh[NB * NHEADS * NS * DHEAD];              // V single fp16
__device__ __nv_bfloat16 g_ah[MTOT * NHID], g_al[MTOT * NHID];        // attn out bf16 hi/lo

// ===========================================================================
// Helpers
// ===========================================================================
__device__ __forceinline__ uint32_t smem_to_u32(const void* p) {
    uint32_t a;
    asm("{ .reg .u64 t; cvta.to.shared.u64 t, %1; cvt.u32.u64 %0, t; }"
        : "=r"(a) : "l"(p));
    return a;
}
__device__ __forceinline__ void cp_async16(uint32_t s, const void* g) {
    asm volatile("cp.async.cg.shared.global [%0], [%1], 16;" :: "r"(s), "l"(g));
}
__device__ __forceinline__ void cp_commit() {
    asm volatile("cp.async.commit_group;" ::: "memory");
}
template <int N>
__device__ __forceinline__ void cp_wait() {
    asm volatile("cp.async.wait_group %0;" :: "n"(N) : "memory");
}
__device__ __forceinline__ void ldmatrix_x4(uint32_t& d0, uint32_t& d1,
                                            uint32_t& d2, uint32_t& d3,
                                            uint32_t addr) {
    asm volatile("ldmatrix.sync.aligned.m8n8.x4.shared.b16 {%0,%1,%2,%3}, [%4];"
        : "=r"(d0), "=r"(d1), "=r"(d2), "=r"(d3) : "r"(addr));
}
__device__ __forceinline__ void ldmatrix_x4_trans(uint32_t& d0, uint32_t& d1,
                                                  uint32_t& d2, uint32_t& d3,
                                                  uint32_t addr) {
    asm volatile("ldmatrix.sync.aligned.m8n8.x4.trans.shared.b16 {%0,%1,%2,%3}, [%4];"
        : "=r"(d0), "=r"(d1), "=r"(d2), "=r"(d3) : "r"(addr));
}
__device__ __forceinline__ void mma_bf16(float* c, const uint32_t* a,
                                         const uint32_t* b) {
    asm volatile(
        "mma.sync.aligned.m16n8k16.row.col.f32.bf16.bf16.f32 "
        "{%0,%1,%2,%3}, {%4,%5,%6,%7}, {%8,%9}, {%0,%1,%2,%3};"
        : "+f"(c[0]), "+f"(c[1]), "+f"(c[2]), "+f"(c[3])
        : "r"(a[0]), "r"(a[1]), "r"(a[2]), "r"(a[3]), "r"(b[0]), "r"(b[1]));
}
__device__ __forceinline__ void mma_f16(float* c, const uint32_t* a,
                                        const uint32_t* b) {
    asm volatile(
        "mma.sync.aligned.m16n8k16.row.col.f32.f16.f16.f32 "
        "{%0,%1,%2,%3}, {%4,%5,%6,%7}, {%8,%9}, {%0,%1,%2,%3};"
        : "+f"(c[0]), "+f"(c[1]), "+f"(c[2]), "+f"(c[3])
        : "r"(a[0]), "r"(a[1]), "r"(a[2]), "r"(a[3]), "r"(b[0]), "r"(b[1]));
}
__device__ __forceinline__ uint32_t packbf(__nv_bfloat16 x, __nv_bfloat16 y) {
    __nv_bfloat162 p; p.x = x; p.y = y;
    return *reinterpret_cast<uint32_t*>(&p);
}
__device__ __forceinline__ void split2(float x, float y,
                                       uint32_t& hi, uint32_t& lo) {
    __nv_bfloat16 hx = __float2bfloat16_rn(x);
    __nv_bfloat16 hy = __float2bfloat16_rn(y);
    hi = packbf(hx, hy);
    lo = packbf(__float2bfloat16_rn(x - __bfloat162float(hx)),
                __float2bfloat16_rn(y - __bfloat162float(hy)));
}
__device__ __forceinline__ void split4(float4 v, uint2& hi, uint2& lo) {
    split2(v.x, v.y, hi.x, lo.x);
    split2(v.z, v.w, hi.y, lo.y);
}
__device__ __forceinline__ void split2h(float x, float y,
                                        uint32_t& hi, uint32_t& lo) {
    __half hx = __float2half_rn(x);
    __half hy = __float2half_rn(y);
    __half2 p;
    p.x = hx; p.y = hy; hi = *reinterpret_cast<uint32_t*>(&p);
    p.x = __float2half_rn(x - __half2float(hx));
    p.y = __float2half_rn(y - __half2float(hy));
    lo = *reinterpret_cast<uint32_t*>(&p);
}
__device__ __forceinline__ uint32_t f2h2(float x, float y) {
    uint32_t r;
    asm("cvt.rn.f16x2.f32 %0, %1, %2;" : "=r"(r) : "f"(y), "f"(x));
    return r;
}
__device__ __forceinline__ float ex2f(float x) {
    float r;
    asm("ex2.approx.f32 %0, %1;" : "=f"(r) : "f"(x));
    return r;
}
__device__ __forceinline__ uint32_t ex2h2(uint32_t x) {
    uint32_t r;
    asm("ex2.approx.f16x2 %0, %1;" : "=r"(r) : "r"(x));
    return r;
}

#define L2E 1.4426950408889634f

// ===========================================================================
// Split kernels
// ===========================================================================
__global__ __launch_bounds__(256)
void split_kernel(const float* __restrict__ src,
                  __nv_bfloat16* __restrict__ h,
                  __nv_bfloat16* __restrict__ l, int n4)
{
    int i = blockIdx.x * 256 + threadIdx.x;
    if (i < n4) {
        float4 v = ((const float4*)src)[i];
        uint2 hi, lo;
        split4(v, hi, lo);
        ((uint2*)h)[i] = hi;
        ((uint2*)l)[i] = lo;
    }
}

// fp32 -> single fp16
__global__ __launch_bounds__(256)
void cvt_f16_kernel(const float* __restrict__ src,
                    __half* __restrict__ h, int n4)
{
    int i = blockIdx.x * 256 + threadIdx.x;
    if (i < n4) {
        float4 v = ((const float4*)src)[i];
        uint2 o;
        o.x = f2h2(v.x, v.y);
        o.y = f2h2(v.z, v.w);
        ((uint2*)h)[i] = o;
    }
}

// fp32 -> fp16 hi/lo
__global__ __launch_bounds__(256)
void split_f16_kernel(const float* __restrict__ src,
                      __half* __restrict__ h,
                      __half* __restrict__ l, int n4)
{
    int i = blockIdx.x * 256 + threadIdx.x;
    if (i < n4) {
        float4 v = ((const float4*)src)[i];
        uint2 hi, lo;
        split2h(v.x, v.y, hi.x, lo.x);
        split2h(v.z, v.w, hi.y, lo.y);
        ((uint2*)h)[i] = hi;
        ((uint2*)l)[i] = lo;
    }
}

// ===========================================================================
// QKV GEMM (fp16 2-term): D = X*Wh + X*Wl.  X single fp16, W fp16 hi/lo.
// CTA 128x256, warp 64x64, BK=32, 3 stages.
// Scatters Q (bf16 hi/lo, pre-scaled 0.125*log2e), K (bf16 hi/lo),
// V (single fp16) into [B,NH,S,HD].
// ===========================================================================
#define GLDS 40
#define GA_BUF 10240           // 128 rows x 80B (single A)
#define GB_BUF 20480           // 256 rows x 80B
#define QSTAGE (GA_BUF + 2 * GB_BUF)       // 51200
#define QKV_SMEM (3 * QSTAGE)              // 153600

__global__ __launch_bounds__(256, 1)
void gemm_qkv_f16_kernel(const __half* __restrict__ A,
                         const __half* __restrict__ Bh,
                         const __half* __restrict__ Bl)
{
    extern __shared__ char smc[];
    const uint32_t sb = smem_to_u32(smc);

    const int t    = threadIdx.x;
    const int lane = t & 31;
    const int wid  = t >> 5;
    const int wm   = wid & 1;
    const int wn   = wid >> 1;
    const int m0   = blockIdx.y << 7;
    const int n0   = blockIdx.x << 8;

    const int rA = lane & 15;
    const int cA = (lane >> 4) << 3;
    const int rB = (lane & 7) + ((lane >> 4) << 3);
    const int cB = lane & 8;

    auto issue = [&](int c, int stg) {
        const int k0 = c << 5;
        const uint32_t st = sb + stg * QSTAGE;
        // A: 128 rows x 4 chunks = 512 -> 2 iters
#pragma unroll
        for (int j = 0; j < 2; j++) {
            int idx = t + (j << 8);
            int row = idx >> 2, ch = idx & 3;
            uint32_t so = (uint32_t)(row * 80 + ch * 16);
            cp_async16(st + so, A + (size_t)(m0 + row) * NHID + k0 + ch * 8);
        }
        // B: 256 rows x 4 chunks x 2 buffers
#pragma unroll
        for (int j = 0; j < 4; j++) {
            int idx = t + (j << 8);
            int row = idx >> 2, ch = idx & 3;
            uint32_t so = (uint32_t)(row * 80 + ch * 16);
            const size_t go = (size_t)(n0 + row) * NHID + k0 + ch * 8;
            cp_async16(st + GA_BUF + so, Bh + go);
            cp_async16(st + GA_BUF + GB_BUF + so, Bl + go);
        }
        cp_commit();
    };

    float acc[4][8][4];
#pragma unroll
    for (int mf = 0; mf < 4; mf++)
#pragma unroll
        for (int nf = 0; nf < 8; nf++)
#pragma unroll
            for (int r = 0; r < 4; r++) acc[mf][nf][r] = 0.f;

    issue(0, 0);
    issue(1, 1);

    for (int c = 0; c < 32; ++c) {
        if (c < 31) cp_wait<1>(); else cp_wait<0>();
        __syncthreads();
        if (c + 2 < 32) issue(c + 2, (c + 2) % 3);

        const uint32_t st = sb + (c % 3) * QSTAGE;
#pragma unroll
        for (int ks = 0; ks < 2; ks++) {
            const int k0 = ks << 4;
            uint32_t a[4][4];
#pragma unroll
            for (int mf = 0; mf < 4; mf++) {
                uint32_t ro = (uint32_t)((wm * 64 + mf * 16 + rA) * GLDS + k0 + cA) * 2;
                ldmatrix_x4(a[mf][0], a[mf][1], a[mf][2], a[mf][3], st + ro);
            }
#pragma unroll
            for (int p = 0; p < 4; p++) {
                uint32_t ro = (uint32_t)((wn * 64 + p * 16 + rB) * GLDS + k0 + cB) * 2;
                uint32_t h0, h1, h2, h3, e0, e1, e2, e3;
                ldmatrix_x4(h0, h1, h2, h3, st + GA_BUF + ro);
                ldmatrix_x4(e0, e1, e2, e3, st + GA_BUF + GB_BUF + ro);
                uint32_t bh0[2] = {h0, h1}, bh1[2] = {h2, h3};
                uint32_t bl0[2] = {e0, e1}, bl1[2] = {e2, e3};
#pragma unroll
                for (int mf = 0; mf < 4; mf++) {
                    mma_f16(acc[mf][2 * p],     a[mf], bh0);
                    mma_f16(acc[mf][2 * p],     a[mf], bl0);
                    mma_f16(acc[mf][2 * p + 1], a[mf], bh1);
                    mma_f16(acc[mf][2 * p + 1], a[mf], bl1);
                }
            }
        }
    }

    const int rowBase = m0 + wm * 64 + (lane >> 2);
    const int colBase = n0 + wn * 64 + ((lane & 3) << 1);
    const int which = n0 >> 10;     // 0=Q 1=K 2=V (constant per CTA)
    const float sc = (which == 0) ? 0.125f * L2E : 1.0f;

#pragma unroll
    for (int mf = 0; mf < 4; mf++)
#pragma unroll
        for (int nf = 0; nf < 8; nf++) {
            int n = colBase + nf * 8;
            int r = n & 1023;
            int h = r >> 6, d = r & 63;
#pragma unroll
            for (int half = 0; half < 2; half++) {
                int m = rowBase + mf * 16 + half * 8;
                int b = m >> 11, s = m & (NS - 1);
                size_t idx = ((((size_t)(b * NHEADS + h)) * NS + s) << 6) + d;
                if (which == 2) {
                    *(uint32_t*)(g_vh + idx) =
                        f2h2(acc[mf][nf][half * 2], acc[mf][nf][half * 2 + 1]);
                } else {
                    uint32_t hi, lo;
                    split2(acc[mf][nf][half * 2] * sc,
                           acc[mf][nf][half * 2 + 1] * sc, hi, lo);
                    if (which == 0) {
                        *(uint32_t*)(g_qh + idx) = hi;
                        *(uint32_t*)(g_ql + idx) = lo;
                    } else {
                        *(uint32_t*)(g_kh + idx) = hi;
                        *(uint32_t*)(g_kl + idx) = lo;
                    }
                }
            }
        }
}

// ===========================================================================
// Output GEMM (bf16 3-term, unchanged): out = A @ Wo^T -> fp32
// ===========================================================================
#define OSTAGE (2 * GA_BUF + 2 * GB_BUF)   // 61440
#define OUT_SMEM (3 * OSTAGE)              // 184320

__global__ __launch_bounds__(256, 1)
void gemm_out_kernel(const __nv_bfloat16* __restrict__ Ah,
                     const __nv_bfloat16* __restrict__ Al,
                     const __nv_bfloat16* __restrict__ Bh,
                     const __nv_bfloat16* __restrict__ Bl,
                     float* __restrict__ Cf)
{
    extern __shared__ char smc[];
    const uint32_t sb = smem_to_u32(smc);

    const int t    = threadIdx.x;
    const int lane = t & 31;
    const int wid  = t >> 5;
    const int wm   = wid & 1;
    const int wn   = wid >> 1;
    const int m0   = blockIdx.y << 7;
    const int n0   = blockIdx.x << 8;

    const int rA = lane & 15;
    const int cA = (lane >> 4) << 3;
    const int rB = (lane & 7) + ((lane >> 4) << 3);
    const int cB = lane & 8;

    auto issue = [&](int c, int stg) {
        const int k0 = c << 5;
        const uint32_t st = sb + stg * OSTAGE;
#pragma unroll
        for (int j = 0; j < 2; j++) {
            int idx = t + (j << 8);
            int row = idx >> 2, ch = idx & 3;
            uint32_t so = (uint32_t)(row * 80 + ch * 16);
            const size_t go = (size_t)(m0 + row) * NHID + k0 + ch * 8;
            cp_async16(st + so, Ah + go);
            cp_async16(st + GA_BUF + so, Al + go);
        }
#pragma unroll
        for (int j = 0; j < 4; j++) {
            int idx = t + (j << 8);
            int row = idx >> 2, ch = idx & 3;
            uint32_t so = (uint32_t)(row * 80 + ch * 16);
            const size_t go = (size_t)(n0 + row) * NHID + k0 + ch * 8;
            cp_async16(st + 2 * GA_BUF + so, Bh + go);
            cp_async16(st + 2 * GA_BUF + GB_BUF + so, Bl + go);
        }
        cp_commit();
    };

    float acc[4][8][4];
#pragma unroll
    for (int mf = 0; mf < 4; mf++)
#pragma unroll
        for (int nf = 0; nf < 8; nf++)
#pragma unroll
            for (int r = 0; r < 4; r++) acc[mf][nf][r] = 0.f;

    issue(0, 0);
    issue(1, 1);

    for (int c = 0; c < 32; ++c) {
        if (c < 31) cp_wait<1>(); else cp_wait<0>();
        __syncthreads();
        if (c + 2 < 32) issue(c + 2, (c + 2) % 3);

        const uint32_t st = sb + (c % 3) * OSTAGE;
#pragma unroll
        for (int ks = 0; ks < 2; ks++) {
            const int k0 = ks << 4;
            uint32_t ah[4][4], al[4][4];
#pragma unroll
            for (int mf = 0; mf < 4; mf++) {
                uint32_t ro = (uint32_t)((wm * 64 + mf * 16 + rA) * GLDS + k0 + cA) * 2;
                ldmatrix_x4(ah[mf][0], ah[mf][1], ah[mf][2], ah[mf][3], st + ro);
                ldmatrix_x4(al[mf][0], al[mf][1], al[mf][2], al[mf][3], st + GA_BUF + ro);
            }
#pragma unroll
            for (int p = 0; p < 4; p++) {
                uint32_t ro = (uint32_t)((wn * 64 + p * 16 + rB) * GLDS + k0 + cB) * 2;
                uint32_t h0, h1, h2, h3, e0, e1, e2, e3;
                ldmatrix_x4(h0, h1, h2, h3, st + 2 * GA_BUF + ro);
                ldmatrix_x4(e0, e1, e2, e3, st + 2 * GA_BUF + GB_BUF + ro);
                uint32_t bh0[2] = {h0, h1}, bh1[2] = {h2, h3};
                uint32_t bl0[2] = {e0, e1}, bl1[2] = {e2, e3};
#pragma unroll
                for (int mf = 0; mf < 4; mf++) {
                    mma_bf16(acc[mf][2 * p],     ah[mf], bh0);
                    mma_bf16(acc[mf][2 * p],     ah[mf], bl0);
                    mma_bf16(acc[mf][2 * p],     al[mf], bh0);
                    mma_bf16(acc[mf][2 * p + 1], ah[mf], bh1);
                    mma_bf16(acc[mf][2 * p + 1], ah[mf], bl1);
                    mma_bf16(acc[mf][2 * p + 1], al[mf], bh1);
                }
            }
        }
    }

    const int rowBase = m0 + wm * 64 + (lane >> 2);
    const int colBase = n0 + wn * 64 + ((lane & 3) << 1);
#pragma unroll
    for (int mf = 0; mf < 4; mf++)
#pragma unroll
        for (int nf = 0; nf < 8; nf++) {
            int n = colBase + nf * 8;
#pragma unroll
            for (int half = 0; half < 2; half++) {
                int m = rowBase + mf * 16 + half * 8;
                *(float2*)(Cf + (size_t)m * NHID + n) =
                    make_float2(acc[mf][nf][half * 2], acc[mf][nf][half * 2 + 1]);
            }
        }
}

// ===========================================================================
// Flash attention (round-10 best): QK bf16 3-term (log2 domain), exp via
// ex2.approx.f16x2, P fp16, V single fp16 (PV 1-term), l via ones-MMA.
// CTA = (b,h) x 128 q-rows, 8 warps, K-tile 128, cp.async double-buffered.
// ===========================================================================
#define KT 128
#define ALDS 72
#define ABUF (128 * 144)
#define ASTG (3 * ABUF)            // Kh, Kl, Vh
#define OQH 0
#define OQL ABUF
#define OST (2 * ABUF)
#define OMSK (OST + 2 * ASTG)
#define ATTN_SMEM (OMSK + 1024)

__global__ __launch_bounds__(256, 1)
void attn_tc_kernel(const float* __restrict__ mask)
{
    extern __shared__ char smc[];
    const uint32_t sb = smem_to_u32(smc);

    const int t    = threadIdx.x;
    const int lane = t & 31;
    const int w    = t >> 5;

    const int bh = blockIdx.y;
    const int b  = bh >> 4;
    const int h  = bh & 15;
    const int q0 = blockIdx.x << 7;

    const int rA = lane & 15;
    const int cA = (lane >> 4) << 3;
    const int rB = (lane & 7) + ((lane >> 4) << 3);
    const int cB = lane & 8;
    const int c0 = (lane & 3) << 1;

    const size_t qbase  = ((size_t)bh * NS + q0) * DHEAD;
    const size_t kvbase = (size_t)bh * NS * DHEAD;

    auto issue_kv = [&](int kt, int stg) {
        const size_t base = kvbase + (size_t)kt * KT * DHEAD;
        const uint32_t st = sb + OST + stg * ASTG;
#pragma unroll
        for (int j = 0; j < 4; j++) {
            int idx = t + (j << 8);
            int row = idx >> 3, ch = idx & 7;
            uint32_t so = (uint32_t)(row * 144 + ch * 16);
            size_t go = base + row * DHEAD + ch * 8;
            cp_async16(st + 0 * ABUF + so, g_kh + go);
            cp_async16(st + 1 * ABUF + so, g_kl + go);
            cp_async16(st + 2 * ABUF + so, g_vh + go);
        }
        if (t < 32)
            cp_async16(sb + OMSK + stg * 512 + t * 16,
                       mask + (size_t)b * NS + kt * KT + t * 4);
        cp_commit();
    };

#pragma unroll
    for (int j = 0; j < 4; j++) {
        int idx = t + (j << 8);
        int row = idx >> 3, ch = idx & 7;
        uint32_t so = (uint32_t)(row * 144 + ch * 16);
        size_t go = qbase + row * DHEAD + ch * 8;
        cp_async16(sb + OQH + so, g_qh + go);
        cp_async16(sb + OQL + so, g_ql + go);
    }
    issue_kv(0, 0);

    float accs[16][4];
    uint32_t pp[16][2];
    float acco[8][4];
    float acco_l[4] = {0.f, 0.f, 0.f, 0.f};
    float m0 = -INFINITY, m1 = -INFINITY;
#pragma unroll
    for (int nf = 0; nf < 8; nf++)
#pragma unroll
        for (int r = 0; r < 4; r++) acco[nf][r] = 0.f;

    const uint32_t bones[2] = {0x3C003C00u, 0x3C003C00u};

    for (int kt = 0; kt < NS / KT; kt++) {
        cp_wait<0>();
        __syncthreads();
        if (kt + 1 < NS / KT) issue_kv(kt + 1, (kt + 1) & 1);

        const int stg = kt & 1;
        const uint32_t st = sb + OST + stg * ASTG;
        const float* msk = (const float*)(smc + OMSK + stg * 512);

#pragma unroll
        for (int nf = 0; nf < 16; nf++)
#pragma unroll
            for (int r = 0; r < 4; r++) accs[nf][r] = 0.f;

#pragma unroll
        for (int ks = 0; ks < 4; ks++) {
            uint32_t aqh[4], aql[4];
            uint32_t qo = (uint32_t)((w * 16 + rA) * ALDS + ks * 16 + cA) * 2;
            ldmatrix_x4(aqh[0], aqh[1], aqh[2], aqh[3], sb + OQH + qo);
            ldmatrix_x4(aql[0], aql[1], aql[2], aql[3], sb + OQL + qo);
#pragma unroll
            for (int p = 0; p < 8; p++) {
                uint32_t ko = (uint32_t)((p * 16 + rB) * ALDS + ks * 16 + cB) * 2;
                uint32_t h0, h1, h2, h3, e0, e1, e2, e3;
                ldmatrix_x4(h0, h1, h2, h3, st + 0 * ABUF + ko);
                ldmatrix_x4(e0, e1, e2, e3, st + 1 * ABUF + ko);
                uint32_t bhi0[2] = {h0, h1}, bhi1[2] = {h2, h3};
                uint32_t blo0[2] = {e0, e1}, blo1[2] = {e2, e3};
                mma_bf16(accs[2 * p],     aqh, bhi0);
                mma_bf16(accs[2 * p],     aqh, blo0);
                mma_bf16(accs[2 * p],     aql, bhi0);
                mma_bf16(accs[2 * p + 1], aqh, bhi1);
                mma_bf16(accs[2 * p + 1], aqh, blo1);
                mma_bf16(accs[2 * p + 1], aql, bhi1);
            }
        }

#pragma unroll
        for (int nf = 0; nf < 16; nf++) {
            float mk0 = msk[nf * 8 + c0];
            float mk1 = msk[nf * 8 + c0 + 1];
            accs[nf][0] = fmaf(mk0, L2E, accs[nf][0]);
            accs[nf][1] = fmaf(mk1, L2E, accs[nf][1]);
            accs[nf][2] = fmaf(mk0, L2E, accs[nf][2]);
            accs[nf][3] = fmaf(mk1, L2E, accs[nf][3]);
        }

        float tm0 = -INFINITY, tm1 = -INFINITY;
#pragma unroll
        for (int nf = 0; nf < 16; nf++) {
            tm0 = fmaxf(tm0, fmaxf(accs[nf][0], accs[nf][1]));
            tm1 = fmaxf(tm1, fmaxf(accs[nf][2], accs[nf][3]));
        }
        tm0 = fmaxf(tm0, __shfl_xor_sync(0xffffffffu, tm0, 1));
        tm0 = fmaxf(tm0, __shfl_xor_sync(0xffffffffu, tm0, 2));
        tm1 = fmaxf(tm1, __shfl_xor_sync(0xffffffffu, tm1, 1));
        tm1 = fmaxf(tm1, __shfl_xor_sync(0xffffffffu, tm1, 2));

        float mn0 = fmaxf(m0, tm0), mn1 = fmaxf(m1, tm1);
        float cr0 = ex2f(m0 - mn0), cr1 = ex2f(m1 - mn1);
        m0 = mn0; m1 = mn1;

#pragma unroll
        for (int nf = 0; nf < 16; nf++) {
            pp[nf][0] = ex2h2(f2h2(accs[nf][0] - mn0, accs[nf][1] - mn0));
            pp[nf][1] = ex2h2(f2h2(accs[nf][2] - mn1, accs[nf][3] - mn1));
        }

#pragma unroll
        for (int nf = 0; nf < 8; nf++) {
            acco[nf][0] *= cr0; acco[nf][1] *= cr0;
            acco[nf][2] *= cr1; acco[nf][3] *= cr1;
        }
        acco_l[0] *= cr0;
        acco_l[2] *= cr1;

#pragma unroll
        for (int kc = 0; kc < 8; kc++) {
            uint32_t aph[4] = { pp[2 * kc][0], pp[2 * kc][1],
                                pp[2 * kc + 1][0], pp[2 * kc + 1][1] };
            mma_f16(acco_l, aph, bones);
#pragma unroll
            for (int pv = 0; pv < 4; pv++) {
                uint32_t vo = (uint32_t)((kc * 16 + rA) * ALDS + pv * 16 + cA) * 2;
                uint32_t h0, h1, h2, h3;
                ldmatrix_x4_trans(h0, h1, h2, h3, st + 2 * ABUF + vo);
                uint32_t bvh0[2] = {h0, h1}, bvh1[2] = {h2, h3};
                mma_f16(acco[2 * pv],     aph, bvh0);
                mma_f16(acco[2 * pv + 1], aph, bvh1);
            }
        }
    }

    float inv0 = 1.f / acco_l[0];
    float inv1 = 1.f / acco_l[2];
    int row0 = q0 + w * 16 + (lane >> 2);
#pragma unroll
    for (int nf = 0; nf < 8; nf++) {
        int d = nf * 8 + c0;
        size_t i0 = ((size_t)(b * NS) + row0) * NHID + h * DHEAD + d;
        size_t i1 = i0 + (size_t)8 * NHID;
        uint32_t hi, lo;
        split2(acco[nf][0] * inv0, acco[nf][1] * inv0, hi, lo);
        *(uint32_t*)(g_ah + i0) = hi;
        *(uint32_t*)(g_al + i0) = lo;
        split2(acco[nf][2] * inv1, acco[nf][3] * inv1, hi, lo);
        *(uint32_t*)(g_ah + i1) = hi;
        *(uint32_t*)(g_al + i1) = lo;
    }
}

// ---------------------------------------------------------------------------
// Launch
// ---------------------------------------------------------------------------
extern "C" void kernel_launch(void* const* d_in, const int* in_sizes, int n_in,
                              void* d_out, int out_size)
{
    const float* X    = (const float*)d_in[0];
    const float* mask = (const float*)d_in[1];
    const float* Wq   = (const float*)d_in[2];
    const float* Wk   = (const float*)d_in[3];
    const float* Wv   = (const float*)d_in[4];
    const float* Wo   = (const float*)d_in[5];
    float* out = (float*)d_out;

    __half *x16, *wh16, *wl16;
    __nv_bfloat16 *woh, *wol, *ah, *al;
    cudaGetSymbolAddress((void**)&x16,  g_x16);
    cudaGetSymbolAddress((void**)&wh16, g_wh16);
    cudaGetSymbolAddress((void**)&wl16, g_wl16);
    cudaGetSymbolAddress((void**)&woh,  g_woh);
    cudaGetSymbolAddress((void**)&wol,  g_wol);
    cudaGetSymbolAddress((void**)&ah,   g_ah);
    cudaGetSymbolAddress((void**)&al,   g_al);

    cudaFuncSetAttribute(gemm_qkv_f16_kernel,
                         cudaFuncAttributeMaxDynamicSharedMemorySize, QKV_SMEM);
    cudaFuncSetAttribute(gemm_out_kernel,
                         cudaFuncAttributeMaxDynamicSharedMemorySize, OUT_SMEM);
    cudaFuncSetAttribute(attn_tc_kernel,
                         cudaFuncAttributeMaxDynamicSharedMemorySize, ATTN_SMEM);

    int n4x = MTOT * NHID / 4;
    int n4w = NHID * NHID / 4;
    cvt_f16_kernel<<<n4x / 256, 256>>>(X, x16, n4x);
    split_f16_kernel<<<n4w / 256, 256>>>(Wq, wh16,                 wl16,                 n4w);
    split_f16_kernel<<<n4w / 256, 256>>>(Wk, wh16 + NHID*NHID,     wl16 + NHID*NHID,     n4w);
    split_f16_kernel<<<n4w / 256, 256>>>(Wv, wh16 + 2*NHID*NHID,   wl16 + 2*NHID*NHID,   n4w);
    split_kernel<<<n4w / 256, 256>>>(Wo, woh, wol, n4w);

    dim3 gq(3 * NHID / 256, MTOT / 128);   // 12 x 64
    gemm_qkv_f16_kernel<<<gq, 256, QKV_SMEM>>>(x16, wh16, wl16);

    dim3 ga(NS / KT, NB * NHEADS);         // 16 x 64
    attn_tc_kernel<<<ga, 256, ATTN_SMEM>>>(mask);

    dim3 go(NHID / 256, MTOT / 128);       // 4 x 64
    gemm_out_kernel<<<go, 256, OUT_SMEM>>>(ah, al, woh, wol, out);
}

// round 13
// speedup vs baseline: 1.1984x; 1.0543x over previous
#include <cuda_runtime.h>
#include <cuda_bf16.h>
#include <cuda_fp16.h>
#include <cstdint>
#include <math.h>

#define NB 4
#define NS 2048
#define NHID 1024
#define NHEADS 16
#define DHEAD 64
#define MTOT (NB * NS)   // 8192

// ---------------------------------------------------------------------------
// Global scratch
// ---------------------------------------------------------------------------
__device__ __half        g_x16[MTOT * NHID];                               // X single fp16
__device__ __half        g_wh16[3 * NHID * NHID], g_wl16[3 * NHID * NHID]; // Wq|Wk|Wv fp16 hi/lo
__device__ __half        g_wo16h[NHID * NHID], g_wo16l[NHID * NHID];       // Wo fp16 hi/lo
__device__ __nv_bfloat16 g_qh[NB * NHEADS * NS * DHEAD], g_ql[NB * NHEADS * NS * DHEAD];
__device__ __nv_bfloat16 g_kh[NB * NHEADS * NS * DHEAD], g_kl[NB * NHEADS * NS * DHEAD];
__device__ __half        g_vh[NB * NHEADS * NS * DHEAD];                   // V single fp16
__device__ __half        g_a16[MTOT * NHID];                               // attn out single fp16

// ===========================================================================
// Helpers
// ===========================================================================
__device__ __forceinline__ uint32_t smem_to_u32(const void* p) {
    uint32_t a;
    asm("{ .reg .u64 t; cvta.to.shared.u64 t, %1; cvt.u32.u64 %0, t; }"
        : "=r"(a) : "l"(p));
    return a;
}
__device__ __forceinline__ void cp_async16(uint32_t s, const void* g) {
    asm volatile("cp.async.cg.shared.global [%0], [%1], 16;" :: "r"(s), "l"(g));
}
__device__ __forceinline__ void cp_commit() {
    asm volatile("cp.async.commit_group;" ::: "memory");
}
template <int N>
__device__ __forceinline__ void cp_wait() {
    asm volatile("cp.async.wait_group %0;" :: "n"(N) : "memory");
}
__device__ __forceinline__ void ldmatrix_x4(uint32_t& d0, uint32_t& d1,
                                            uint32_t& d2, uint32_t& d3,
                                            uint32_t addr) {
    asm volatile("ldmatrix.sync.aligned.m8n8.x4.shared.b16 {%0,%1,%2,%3}, [%4];"
        : "=r"(d0), "=r"(d1), "=r"(d2), "=r"(d3) : "r"(addr));
}
__device__ __forceinline__ void ldmatrix_x4_trans(uint32_t& d0, uint32_t& d1,
                                                  uint32_t& d2, uint32_t& d3,
                                                  uint32_t addr) {
    asm volatile("ldmatrix.sync.aligned.m8n8.x4.trans.shared.b16 {%0,%1,%2,%3}, [%4];"
        : "=r"(d0), "=r"(d1), "=r"(d2), "=r"(d3) : "r"(addr));
}
__device__ __forceinline__ void mma_bf16(float* c, const uint32_t* a,
                                         const uint32_t* b) {
    asm volatile(
        "mma.sync.aligned.m16n8k16.row.col.f32.bf16.bf16.f32 "
        "{%0,%1,%2,%3}, {%4,%5,%6,%7}, {%8,%9}, {%0,%1,%2,%3};"
        : "+f"(c[0]), "+f"(c[1]), "+f"(c[2]), "+f"(c[3])
        : "r"(a[0]), "r"(a[1]), "r"(a[2]), "r"(a[3]), "r"(b[0]), "r"(b[1]));
}
__device__ __forceinline__ void mma_f16(float* c, const uint32_t* a,
                                        const uint32_t* b) {
    asm volatile(
        "mma.sync.aligned.m16n8k16.row.col.f32.f16.f16.f32 "
        "{%0,%1,%2,%3}, {%4,%5,%6,%7}, {%8,%9}, {%0,%1,%2,%3};"
        : "+f"(c[0]), "+f"(c[1]), "+f"(c[2]), "+f"(c[3])
        : "r"(a[0]), "r"(a[1]), "r"(a[2]), "r"(a[3]), "r"(b[0]), "r"(b[1]));
}
__device__ __forceinline__ uint32_t packbf(__nv_bfloat16 x, __nv_bfloat16 y) {
    __nv_bfloat162 p; p.x = x; p.y = y;
    return *reinterpret_cast<uint32_t*>(&p);
}
__device__ __forceinline__ void split2(float x, float y,
                                       uint32_t& hi, uint32_t& lo) {
    __nv_bfloat16 hx = __float2bfloat16_rn(x);
    __nv_bfloat16 hy = __float2bfloat16_rn(y);
    hi = packbf(hx, hy);
    lo = packbf(__float2bfloat16_rn(x - __bfloat162float(hx)),
                __float2bfloat16_rn(y - __bfloat162float(hy)));
}
__device__ __forceinline__ void split2h(float x, float y,
                                        uint32_t& hi, uint32_t& lo) {
    __half hx = __float2half_rn(x);
    __half hy = __float2half_rn(y);
    __half2 p;
    p.x = hx; p.y = hy; hi = *reinterpret_cast<uint32_t*>(&p);
    p.x = __float2half_rn(x - __half2float(hx));
    p.y = __float2half_rn(y - __half2float(hy));
    lo = *reinterpret_cast<uint32_t*>(&p);
}
__device__ __forceinline__ uint32_t f2h2(float x, float y) {
    uint32_t r;
    asm("cvt.rn.f16x2.f32 %0, %1, %2;" : "=r"(r) : "f"(y), "f"(x));
    return r;
}
__device__ __forceinline__ float ex2f(float x) {
    float r;
    asm("ex2.approx.f32 %0, %1;" : "=f"(r) : "f"(x));
    return r;
}
__device__ __forceinline__ uint32_t ex2h2(uint32_t x) {
    uint32_t r;
    asm("ex2.approx.f16x2 %0, %1;" : "=r"(r) : "r"(x));
    return r;
}

#define L2E 1.4426950408889634f

// ===========================================================================
// Conversion kernels
// ===========================================================================
__global__ __launch_bounds__(256)
void cvt_f16_kernel(const float* __restrict__ src,
                    __half* __restrict__ h, int n4)
{
    int i = blockIdx.x * 256 + threadIdx.x;
    if (i < n4) {
        float4 v = ((const float4*)src)[i];
        uint2 o;
        o.x = f2h2(v.x, v.y);
        o.y = f2h2(v.z, v.w);
        ((uint2*)h)[i] = o;
    }
}

__global__ __launch_bounds__(256)
void split_f16_kernel(const float* __restrict__ src,
                      __half* __restrict__ h,
                      __half* __restrict__ l, int n4)
{
    int i = blockIdx.x * 256 + threadIdx.x;
    if (i < n4) {
        float4 v = ((const float4*)src)[i];
        uint2 hi, lo;
        split2h(v.x, v.y, hi.x, lo.x);
        split2h(v.z, v.w, hi.y, lo.y);
        ((uint2*)h)[i] = hi;
        ((uint2*)l)[i] = lo;
    }
}

// ===========================================================================
// fp16 2-term GEMM: D = A*Bh + A*Bl.  A single fp16, B fp16 hi/lo.
// CTA 128x256, warp 64x64, BK=32, 3 stages.
// qkvMode=1: scatter Q (bf16 hi/lo, pre-scaled 0.125*log2e), K (bf16 hi/lo),
//            V (single fp16) into [B,NH,S,HD].
// qkvMode=0: fp32 out to Cf.
// ===========================================================================
#define GLDS 40
#define GA_BUF 10240           // 128 rows x 80B (single A)
#define GB_BUF 20480           // 256 rows x 80B
#define QSTAGE (GA_BUF + 2 * GB_BUF)       // 51200
#define GEMM_SMEM (3 * QSTAGE)             // 153600

__global__ __launch_bounds__(256, 1)
void gemm_f16_kernel(const __half* __restrict__ A,
                     const __half* __restrict__ Bh,
                     const __half* __restrict__ Bl,
                     float* __restrict__ Cf, int qkvMode)
{
    extern __shared__ char smc[];
    const uint32_t sb = smem_to_u32(smc);

    const int t    = threadIdx.x;
    const int lane = t & 31;
    const int wid  = t >> 5;
    const int wm   = wid & 1;
    const int wn   = wid >> 1;
    const int m0   = blockIdx.y << 7;
    const int n0   = blockIdx.x << 8;

    const int rA = lane & 15;
    const int cA = (lane >> 4) << 3;
    const int rB = (lane & 7) + ((lane >> 4) << 3);
    const int cB = lane & 8;

    auto issue = [&](int c, int stg) {
        const int k0 = c << 5;
        const uint32_t st = sb + stg * QSTAGE;
#pragma unroll
        for (int j = 0; j < 2; j++) {
            int idx = t + (j << 8);
            int row = idx >> 2, ch = idx & 3;
            uint32_t so = (uint32_t)(row * 80 + ch * 16);
            cp_async16(st + so, A + (size_t)(m0 + row) * NHID + k0 + ch * 8);
        }
#pragma unroll
        for (int j = 0; j < 4; j++) {
            int idx = t + (j << 8);
            int row = idx >> 2, ch = idx & 3;
            uint32_t so = (uint32_t)(row * 80 + ch * 16);
            const size_t go = (size_t)(n0 + row) * NHID + k0 + ch * 8;
            cp_async16(st + GA_BUF + so, Bh + go);
            cp_async16(st + GA_BUF + GB_BUF + so, Bl + go);
        }
        cp_commit();
    };

    float acc[4][8][4];
#pragma unroll
    for (int mf = 0; mf < 4; mf++)
#pragma unroll
        for (int nf = 0; nf < 8; nf++)
#pragma unroll
            for (int r = 0; r < 4; r++) acc[mf][nf][r] = 0.f;

    issue(0, 0);
    issue(1, 1);

    for (int c = 0; c < 32; ++c) {
        if (c < 31) cp_wait<1>(); else cp_wait<0>();
        __syncthreads();
        if (c + 2 < 32) issue(c + 2, (c + 2) % 3);

        const uint32_t st = sb + (c % 3) * QSTAGE;
#pragma unroll
        for (int ks = 0; ks < 2; ks++) {
            const int k0 = ks << 4;
            uint32_t a[4][4];
#pragma unroll
            for (int mf = 0; mf < 4; mf++) {
                uint32_t ro = (uint32_t)((wm * 64 + mf * 16 + rA) * GLDS + k0 + cA) * 2;
                ldmatrix_x4(a[mf][0], a[mf][1], a[mf][2], a[mf][3], st + ro);
            }
#pragma unroll
            for (int p = 0; p < 4; p++) {
                uint32_t ro = (uint32_t)((wn * 64 + p * 16 + rB) * GLDS + k0 + cB) * 2;
                uint32_t h0, h1, h2, h3, e0, e1, e2, e3;
                ldmatrix_x4(h0, h1, h2, h3, st + GA_BUF + ro);
                ldmatrix_x4(e0, e1, e2, e3, st + GA_BUF + GB_BUF + ro);
                uint32_t bh0[2] = {h0, h1}, bh1[2] = {h2, h3};
                uint32_t bl0[2] = {e0, e1}, bl1[2] = {e2, e3};
#pragma unroll
                for (int mf = 0; mf < 4; mf++) {
                    mma_f16(acc[mf][2 * p],     a[mf], bh0);
                    mma_f16(acc[mf][2 * p],     a[mf], bl0);
                    mma_f16(acc[mf][2 * p + 1], a[mf], bh1);
                    mma_f16(acc[mf][2 * p + 1], a[mf], bl1);
                }
            }
        }
    }

    const int rowBase = m0 + wm * 64 + (lane >> 2);
    const int colBase = n0 + wn * 64 + ((lane & 3) << 1);

    if (qkvMode) {
        const int which = n0 >> 10;     // 0=Q 1=K 2=V (constant per CTA)
        const float sc = (which == 0) ? 0.125f * L2E : 1.0f;
#pragma unroll
        for (int mf = 0; mf < 4; mf++)
#pragma unroll
            for (int nf = 0; nf < 8; nf++) {
                int n = colBase + nf * 8;
                int r = n & 1023;
                int h = r >> 6, d = r & 63;
#pragma unroll
                for (int half = 0; half < 2; half++) {
                    int m = rowBase + mf * 16 + half * 8;
                    int b = m >> 11, s = m & (NS - 1);
                    size_t idx = ((((size_t)(b * NHEADS + h)) * NS + s) << 6) + d;
                    if (which == 2) {
                        *(uint32_t*)(g_vh + idx) =
                            f2h2(acc[mf][nf][half * 2], acc[mf][nf][half * 2 + 1]);
                    } else {
                        uint32_t hi, lo;
                        split2(acc[mf][nf][half * 2] * sc,
                               acc[mf][nf][half * 2 + 1] * sc, hi, lo);
                        if (which == 0) {
                            *(uint32_t*)(g_qh + idx) = hi;
                            *(uint32_t*)(g_ql + idx) = lo;
                        } else {
                            *(uint32_t*)(g_kh + idx) = hi;
                            *(uint32_t*)(g_kl + idx) = lo;
                        }
                    }
                }
            }
    } else {
#pragma unroll
        for (int mf = 0; mf < 4; mf++)
#pragma unroll
            for (int nf = 0; nf < 8; nf++) {
                int n = colBase + nf * 8;
#pragma unroll
                for (int half = 0; half < 2; half++) {
                    int m = rowBase + mf * 16 + half * 8;
                    *(float2*)(Cf + (size_t)m * NHID + n) =
                        make_float2(acc[mf][nf][half * 2], acc[mf][nf][half * 2 + 1]);
                }
            }
    }
}

// ===========================================================================
// Flash attention (round-10 best): QK bf16 3-term (log2 domain), exp via
// ex2.approx.f16x2, P fp16, V single fp16 (PV 1-term), l via ones-MMA.
// Output written as SINGLE fp16 (feeds fp16 2-term out-GEMM).
// CTA = (b,h) x 128 q-rows, 8 warps, K-tile 128, cp.async double-buffered.
// ===========================================================================
#define KT 128
#define ALDS 72
#define ABUF (128 * 144)
#define ASTG (3 * ABUF)            // Kh, Kl, Vh
#define OQH 0
#define OQL ABUF
#define OST (2 * ABUF)
#define OMSK (OST + 2 * ASTG)
#define ATTN_SMEM (OMSK + 1024)

__global__ __launch_bounds__(256, 1)
void attn_tc_kernel(const float* __restrict__ mask)
{
    extern __shared__ char smc[];
    const uint32_t sb = smem_to_u32(smc);

    const int t    = threadIdx.x;
    const int lane = t & 31;
    const int w    = t >> 5;

    const int bh = blockIdx.y;
    const int b  = bh >> 4;
    const int h  = bh & 15;
    const int q0 = blockIdx.x << 7;

    const int rA = lane & 15;
    const int cA = (lane >> 4) << 3;
    const int rB = (lane & 7) + ((lane >> 4) << 3);
    const int cB = lane & 8;
    const int c0 = (lane & 3) << 1;

    const size_t qbase  = ((size_t)bh * NS + q0) * DHEAD;
    const size_t kvbase = (size_t)bh * NS * DHEAD;

    auto issue_kv = [&](int kt, int stg) {
        const size_t base = kvbase + (size_t)kt * KT * DHEAD;
        const uint32_t st = sb + OST + stg * ASTG;
#pragma unroll
        for (int j = 0; j < 4; j++) {
            int idx = t + (j << 8);
            int row = idx >> 3, ch = idx & 7;
            uint32_t so = (uint32_t)(row * 144 + ch * 16);
            size_t go = base + row * DHEAD + ch * 8;
            cp_async16(st + 0 * ABUF + so, g_kh + go);
            cp_async16(st + 1 * ABUF + so, g_kl + go);
            cp_async16(st + 2 * ABUF + so, g_vh + go);
        }
        if (t < 32)
            cp_async16(sb + OMSK + stg * 512 + t * 16,
                       mask + (size_t)b * NS + kt * KT + t * 4);
        cp_commit();
    };

#pragma unroll
    for (int j = 0; j < 4; j++) {
        int idx = t + (j << 8);
        int row = idx >> 3, ch = idx & 7;
        uint32_t so = (uint32_t)(row * 144 + ch * 16);
        size_t go = qbase + row * DHEAD + ch * 8;
        cp_async16(sb + OQH + so, g_qh + go);
        cp_async16(sb + OQL + so, g_ql + go);
    }
    issue_kv(0, 0);

    float accs[16][4];
    uint32_t pp[16][2];
    float acco[8][4];
    float acco_l[4] = {0.f, 0.f, 0.f, 0.f};
    float m0 = -INFINITY, m1 = -INFINITY;
#pragma unroll
    for (int nf = 0; nf < 8; nf++)
#pragma unroll
        for (int r = 0; r < 4; r++) acco[nf][r] = 0.f;

    const uint32_t bones[2] = {0x3C003C00u, 0x3C003C00u};

    for (int kt = 0; kt < NS / KT; kt++) {
        cp_wait<0>();
        __syncthreads();
        if (kt + 1 < NS / KT) issue_kv(kt + 1, (kt + 1) & 1);

        const int stg = kt & 1;
        const uint32_t st = sb + OST + stg * ASTG;
        const float* msk = (const float*)(smc + OMSK + stg * 512);

#pragma unroll
        for (int nf = 0; nf < 16; nf++)
#pragma unroll
            for (int r = 0; r < 4; r++) accs[nf][r] = 0.f;

#pragma unroll
        for (int ks = 0; ks < 4; ks++) {
            uint32_t aqh[4], aql[4];
            uint32_t qo = (uint32_t)((w * 16 + rA) * ALDS + ks * 16 + cA) * 2;
            ldmatrix_x4(aqh[0], aqh[1], aqh[2], aqh[3], sb + OQH + qo);
            ldmatrix_x4(aql[0], aql[1], aql[2], aql[3], sb + OQL + qo);
#pragma unroll
            for (int p = 0; p < 8; p++) {
                uint32_t ko = (uint32_t)((p * 16 + rB) * ALDS + ks * 16 + cB) * 2;
                uint32_t h0, h1, h2, h3, e0, e1, e2, e3;
                ldmatrix_x4(h0, h1, h2, h3, st + 0 * ABUF + ko);
                ldmatrix_x4(e0, e1, e2, e3, st + 1 * ABUF + ko);
                uint32_t bhi0[2] = {h0, h1}, bhi1[2] = {h2, h3};
                uint32_t blo0[2] = {e0, e1}, blo1[2] = {e2, e3};
                mma_bf16(accs[2 * p],     aqh, bhi0);
                mma_bf16(accs[2 * p],     aqh, blo0);
                mma_bf16(accs[2 * p],     aql, bhi0);
                mma_bf16(accs[2 * p + 1], aqh, bhi1);
                mma_bf16(accs[2 * p + 1], aqh, blo1);
                mma_bf16(accs[2 * p + 1], aql, bhi1);
            }
        }

#pragma unroll
        for (int nf = 0; nf < 16; nf++) {
            float mk0 = msk[nf * 8 + c0];
            float mk1 = msk[nf * 8 + c0 + 1];
            accs[nf][0] = fmaf(mk0, L2E, accs[nf][0]);
            accs[nf][1] = fmaf(mk1, L2E, accs[nf][1]);
            accs[nf][2] = fmaf(mk0, L2E, accs[nf][2]);
            accs[nf][3] = fmaf(mk1, L2E, accs[nf][3]);
        }

        float tm0 = -INFINITY, tm1 = -INFINITY;
#pragma unroll
        for (int nf = 0; nf < 16; nf++) {
            tm0 = fmaxf(tm0, fmaxf(accs[nf][0], accs[nf][1]));
            tm1 = fmaxf(tm1, fmaxf(accs[nf][2], accs[nf][3]));
        }
        tm0 = fmaxf(tm0, __shfl_xor_sync(0xffffffffu, tm0, 1));
        tm0 = fmaxf(tm0, __shfl_xor_sync(0xffffffffu, tm0, 2));
        tm1 = fmaxf(tm1, __shfl_xor_sync(0xffffffffu, tm1, 1));
        tm1 = fmaxf(tm1, __shfl_xor_sync(0xffffffffu, tm1, 2));

        float mn0 = fmaxf(m0, tm0), mn1 = fmaxf(m1, tm1);
        float cr0 = ex2f(m0 - mn0), cr1 = ex2f(m1 - mn1);
        m0 = mn0; m1 = mn1;

#pragma unroll
        for (int nf = 0; nf < 16; nf++) {
            pp[nf][0] = ex2h2(f2h2(accs[nf][0] - mn0, accs[nf][1] - mn0));
            pp[nf][1] = ex2h2(f2h2(accs[nf][2] - mn1, accs[nf][3] - mn1));
        }

#pragma unroll
        for (int nf = 0; nf < 8; nf++) {
            acco[nf][0] *= cr0; acco[nf][1] *= cr0;
            acco[nf][2] *= cr1; acco[nf][3] *= cr1;
        }
        acco_l[0] *= cr0;
        acco_l[2] *= cr1;

#pragma unroll
        for (int kc = 0; kc < 8; kc++) {
            uint32_t aph[4] = { pp[2 * kc][0], pp[2 * kc][1],
                                pp[2 * kc + 1][0], pp[2 * kc + 1][1] };
            mma_f16(acco_l, aph, bones);
#pragma unroll
            for (int pv = 0; pv < 4; pv++) {
                uint32_t vo = (uint32_t)((kc * 16 + rA) * ALDS + pv * 16 + cA) * 2;
                uint32_t h0, h1, h2, h3;
                ldmatrix_x4_trans(h0, h1, h2, h3, st + 2 * ABUF + vo);
                uint32_t bvh0[2] = {h0, h1}, bvh1[2] = {h2, h3};
                mma_f16(acco[2 * pv],     aph, bvh0);
                mma_f16(acco[2 * pv + 1], aph, bvh1);
            }
        }
    }

    // ---- epilogue: single-fp16 output ----
    float inv0 = 1.f / acco_l[0];
    float inv1 = 1.f / acco_l[2];
    int row0 = q0 + w * 16 + (lane >> 2);
#pragma unroll
    for (int nf = 0; nf < 8; nf++) {
        int d = nf * 8 + c0;
        size_t i0 = ((size_t)(b * NS) + row0) * NHID + h * DHEAD + d;
        size_t i1 = i0 + (size_t)8 * NHID;
        *(uint32_t*)(g_a16 + i0) = f2h2(acco[nf][0] * inv0, acco[nf][1] * inv0);
        *(uint32_t*)(g_a16 + i1) = f2h2(acco[nf][2] * inv1, acco[nf][3] * inv1);
    }
}

// ---------------------------------------------------------------------------
// Launch
// ---------------------------------------------------------------------------
extern "C" void kernel_launch(void* const* d_in, const int* in_sizes, int n_in,
                              void* d_out, int out_size)
{
    const float* X    = (const float*)d_in[0];
    const float* mask = (const float*)d_in[1];
    const float* Wq   = (const float*)d_in[2];
    const float* Wk   = (const float*)d_in[3];
    const float* Wv   = (const float*)d_in[4];
    const float* Wo   = (const float*)d_in[5];
    float* out = (float*)d_out;

    __half *x16, *wh16, *wl16, *wo16h, *wo16l, *a16;
    cudaGetSymbolAddress((void**)&x16,   g_x16);
    cudaGetSymbolAddress((void**)&wh16,  g_wh16);
    cudaGetSymbolAddress((void**)&wl16,  g_wl16);
    cudaGetSymbolAddress((void**)&wo16h, g_wo16h);
    cudaGetSymbolAddress((void**)&wo16l, g_wo16l);
    cudaGetSymbolAddress((void**)&a16,   g_a16);

    cudaFuncSetAttribute(gemm_f16_kernel,
                         cudaFuncAttributeMaxDynamicSharedMemorySize, GEMM_SMEM);
    cudaFuncSetAttribute(attn_tc_kernel,
                         cudaFuncAttributeMaxDynamicSharedMemorySize, ATTN_SMEM);

    int n4x = MTOT * NHID / 4;
    int n4w = NHID * NHID / 4;
    cvt_f16_kernel<<<n4x / 256, 256>>>(X, x16, n4x);
    split_f16_kernel<<<n4w / 256, 256>>>(Wq, wh16,               wl16,               n4w);
    split_f16_kernel<<<n4w / 256, 256>>>(Wk, wh16 + NHID*NHID,   wl16 + NHID*NHID,   n4w);
    split_f16_kernel<<<n4w / 256, 256>>>(Wv, wh16 + 2*NHID*NHID, wl16 + 2*NHID*NHID, n4w);
    split_f16_kernel<<<n4w / 256, 256>>>(Wo, wo16h, wo16l, n4w);

    // fused QKV GEMM
    dim3 gq(3 * NHID / 256, MTOT / 128);   // 12 x 64
    gemm_f16_kernel<<<gq, 256, GEMM_SMEM>>>(x16, wh16, wl16, nullptr, 1);

    // attention
    dim3 ga(NS / KT, NB * NHEADS);         // 16 x 64
    attn_tc_kernel<<<ga, 256, ATTN_SMEM>>>(mask);

    // output projection
    dim3 go(NHID / 256, MTOT / 128);       // 4 x 64
    gemm_f16_kernel<<<go, 256, GEMM_SMEM>>>(a16, wo16h, wo16l, out, 0);
}

// round 14
// speedup vs baseline: 1.4384x; 1.2003x over previous
#include <cuda_runtime.h>
#include <cuda_bf16.h>
#include <cuda_fp16.h>
#include <cstdint>
#include <math.h>

#define NB 4
#define NS 2048
#define NHID 1024
#define NHEADS 16
#define DHEAD 64
#define MTOT (NB * NS)   // 8192

// ---------------------------------------------------------------------------
// Global scratch
// ---------------------------------------------------------------------------
__device__ __half g_x16[MTOT * NHID];                               // X single fp16
__device__ __half g_wh16[3 * NHID * NHID], g_wl16[3 * NHID * NHID]; // Wq|Wk|Wv fp16 hi/lo
__device__ __half g_wo16h[NHID * NHID], g_wo16l[NHID * NHID];       // Wo fp16 hi/lo
__device__ __half g_q16[NB * NHEADS * NS * DHEAD];                  // Q single fp16 (pre-scaled)
__device__ __half g_k16[NB * NHEADS * NS * DHEAD];                  // K single fp16
__device__ __half g_v16[NB * NHEADS * NS * DHEAD];                  // V single fp16
__device__ __half g_a16[MTOT * NHID];                               // attn out single fp16

// ===========================================================================
// Helpers
// ===========================================================================
__device__ __forceinline__ uint32_t smem_to_u32(const void* p) {
    uint32_t a;
    asm("{ .reg .u64 t; cvta.to.shared.u64 t, %1; cvt.u32.u64 %0, t; }"
        : "=r"(a) : "l"(p));
    return a;
}
__device__ __forceinline__ void cp_async16(uint32_t s, const void* g) {
    asm volatile("cp.async.cg.shared.global [%0], [%1], 16;" :: "r"(s), "l"(g));
}
__device__ __forceinline__ void cp_commit() {
    asm volatile("cp.async.commit_group;" ::: "memory");
}
template <int N>
__device__ __forceinline__ void cp_wait() {
    asm volatile("cp.async.wait_group %0;" :: "n"(N) : "memory");
}
__device__ __forceinline__ void ldmatrix_x4(uint32_t& d0, uint32_t& d1,
                                            uint32_t& d2, uint32_t& d3,
                                            uint32_t addr) {
    asm volatile("ldmatrix.sync.aligned.m8n8.x4.shared.b16 {%0,%1,%2,%3}, [%4];"
        : "=r"(d0), "=r"(d1), "=r"(d2), "=r"(d3) : "r"(addr));
}
__device__ __forceinline__ void ldmatrix_x4_trans(uint32_t& d0, uint32_t& d1,
                                                  uint32_t& d2, uint32_t& d3,
                                                  uint32_t addr) {
    asm volatile("ldmatrix.sync.aligned.m8n8.x4.trans.shared.b16 {%0,%1,%2,%3}, [%4];"
        : "=r"(d0), "=r"(d1), "=r"(d2), "=r"(d3) : "r"(addr));
}
__device__ __forceinline__ void mma_f16(float* c, const uint32_t* a,
                                        const uint32_t* b) {
    asm volatile(
        "mma.sync.aligned.m16n8k16.row.col.f32.f16.f16.f32 "
        "{%0,%1,%2,%3}, {%4,%5,%6,%7}, {%8,%9}, {%0,%1,%2,%3};"
        : "+f"(c[0]), "+f"(c[1]), "+f"(c[2]), "+f"(c[3])
        : "r"(a[0]), "r"(a[1]), "r"(a[2]), "r"(a[3]), "r"(b[0]), "r"(b[1]));
}
__device__ __forceinline__ void split2h(float x, float y,
                                        uint32_t& hi, uint32_t& lo) {
    __half hx = __float2half_rn(x);
    __half hy = __float2half_rn(y);
    __half2 p;
    p.x = hx; p.y = hy; hi = *reinterpret_cast<uint32_t*>(&p);
    p.x = __float2half_rn(x - __half2float(hx));
    p.y = __float2half_rn(y - __half2float(hy));
    lo = *reinterpret_cast<uint32_t*>(&p);
}
__device__ __forceinline__ uint32_t f2h2(float x, float y) {
    uint32_t r;
    asm("cvt.rn.f16x2.f32 %0, %1, %2;" : "=r"(r) : "f"(y), "f"(x));
    return r;
}
__device__ __forceinline__ float ex2f(float x) {
    float r;
    asm("ex2.approx.f32 %0, %1;" : "=f"(r) : "f"(x));
    return r;
}
__device__ __forceinline__ uint32_t ex2h2(uint32_t x) {
    uint32_t r;
    asm("ex2.approx.f16x2 %0, %1;" : "=r"(r) : "r"(x));
    return r;
}

#define L2E 1.4426950408889634f

// ===========================================================================
// Conversion kernels
// ===========================================================================
__global__ __launch_bounds__(256)
void cvt_f16_kernel(const float* __restrict__ src,
                    __half* __restrict__ h, int n4)
{
    int i = blockIdx.x * 256 + threadIdx.x;
    if (i < n4) {
        float4 v = ((const float4*)src)[i];
        uint2 o;
        o.x = f2h2(v.x, v.y);
        o.y = f2h2(v.z, v.w);
        ((uint2*)h)[i] = o;
    }
}

__global__ __launch_bounds__(256)
void split_f16_kernel(const float* __restrict__ src,
                      __half* __restrict__ h,
                      __half* __restrict__ l, int n4)
{
    int i = blockIdx.x * 256 + threadIdx.x;
    if (i < n4) {
        float4 v = ((const float4*)src)[i];
        uint2 hi, lo;
        split2h(v.x, v.y, hi.x, lo.x);
        split2h(v.z, v.w, hi.y, lo.y);
        ((uint2*)h)[i] = hi;
        ((uint2*)l)[i] = lo;
    }
}

// ===========================================================================
// fp16 2-term GEMM: D = A*Bh + A*Bl.  A single fp16, B fp16 hi/lo.
// CTA 128x256, warp 64x64, BK=32, 3 stages.
// qkvMode=1: scatter Q (fp16, pre-scaled 0.125*log2e), K (fp16), V (fp16)
//            into [B,NH,S,HD].
// qkvMode=0: fp32 out to Cf.
// ===========================================================================
#define GLDS 40
#define GA_BUF 10240           // 128 rows x 80B (single A)
#define GB_BUF 20480           // 256 rows x 80B
#define QSTAGE (GA_BUF + 2 * GB_BUF)       // 51200
#define GEMM_SMEM (3 * QSTAGE)             // 153600

__global__ __launch_bounds__(256, 1)
void gemm_f16_kernel(const __half* __restrict__ A,
                     const __half* __restrict__ Bh,
                     const __half* __restrict__ Bl,
                     float* __restrict__ Cf, int qkvMode)
{
    extern __shared__ char smc[];
    const uint32_t sb = smem_to_u32(smc);

    const int t    = threadIdx.x;
    const int lane = t & 31;
    const int wid  = t >> 5;
    const int wm   = wid & 1;
    const int wn   = wid >> 1;
    const int m0   = blockIdx.y << 7;
    const int n0   = blockIdx.x << 8;

    const int rA = lane & 15;
    const int cA = (lane >> 4) << 3;
    const int rB = (lane & 7) + ((lane >> 4) << 3);
    const int cB = lane & 8;

    auto issue = [&](int c, int stg) {
        const int k0 = c << 5;
        const uint32_t st = sb + stg * QSTAGE;
#pragma unroll
        for (int j = 0; j < 2; j++) {
            int idx = t + (j << 8);
            int row = idx >> 2, ch = idx & 3;
            uint32_t so = (uint32_t)(row * 80 + ch * 16);
            cp_async16(st + so, A + (size_t)(m0 + row) * NHID + k0 + ch * 8);
        }
#pragma unroll
        for (int j = 0; j < 4; j++) {
            int idx = t + (j << 8);
            int row = idx >> 2, ch = idx & 3;
            uint32_t so = (uint32_t)(row * 80 + ch * 16);
            const size_t go = (size_t)(n0 + row) * NHID + k0 + ch * 8;
            cp_async16(st + GA_BUF + so, Bh + go);
            cp_async16(st + GA_BUF + GB_BUF + so, Bl + go);
        }
        cp_commit();
    };

    float acc[4][8][4];
#pragma unroll
    for (int mf = 0; mf < 4; mf++)
#pragma unroll
        for (int nf = 0; nf < 8; nf++)
#pragma unroll
            for (int r = 0; r < 4; r++) acc[mf][nf][r] = 0.f;

    issue(0, 0);
    issue(1, 1);

    for (int c = 0; c < 32; ++c) {
        if (c < 31) cp_wait<1>(); else cp_wait<0>();
        __syncthreads();
        if (c + 2 < 32) issue(c + 2, (c + 2) % 3);

        const uint32_t st = sb + (c % 3) * QSTAGE;
#pragma unroll
        for (int ks = 0; ks < 2; ks++) {
            const int k0 = ks << 4;
            uint32_t a[4][4];
#pragma unroll
            for (int mf = 0; mf < 4; mf++) {
                uint32_t ro = (uint32_t)((wm * 64 + mf * 16 + rA) * GLDS + k0 + cA) * 2;
                ldmatrix_x4(a[mf][0], a[mf][1], a[mf][2], a[mf][3], st + ro);
            }
#pragma unroll
            for (int p = 0; p < 4; p++) {
                uint32_t ro = (uint32_t)((wn * 64 + p * 16 + rB) * GLDS + k0 + cB) * 2;
                uint32_t h0, h1, h2, h3, e0, e1, e2, e3;
                ldmatrix_x4(h0, h1, h2, h3, st + GA_BUF + ro);
                ldmatrix_x4(e0, e1, e2, e3, st + GA_BUF + GB_BUF + ro);
                uint32_t bh0[2] = {h0, h1}, bh1[2] = {h2, h3};
                uint32_t bl0[2] = {e0, e1}, bl1[2] = {e2, e3};
#pragma unroll
                for (int mf = 0; mf < 4; mf++) {
                    mma_f16(acc[mf][2 * p],     a[mf], bh0);
                    mma_f16(acc[mf][2 * p],     a[mf], bl0);
                    mma_f16(acc[mf][2 * p + 1], a[mf], bh1);
                    mma_f16(acc[mf][2 * p + 1], a[mf], bl1);
                }
            }
        }
    }

    const int rowBase = m0 + wm * 64 + (lane >> 2);
    const int colBase = n0 + wn * 64 + ((lane & 3) << 1);

    if (qkvMode) {
        const int which = n0 >> 10;     // 0=Q 1=K 2=V (constant per CTA)
        const float sc = (which == 0) ? 0.125f * L2E : 1.0f;
        __half* dst = (which == 0) ? g_q16 : (which == 1) ? g_k16 : g_v16;
#pragma unroll
        for (int mf = 0; mf < 4; mf++)
#pragma unroll
            for (int nf = 0; nf < 8; nf++) {
                int n = colBase + nf * 8;
                int r = n & 1023;
                int h = r >> 6, d = r & 63;
#pragma unroll
                for (int half = 0; half < 2; half++) {
                    int m = rowBase + mf * 16 + half * 8;
                    int b = m >> 11, s = m & (NS - 1);
                    size_t idx = ((((size_t)(b * NHEADS + h)) * NS + s) << 6) + d;
                    *(uint32_t*)(dst + idx) =
                        f2h2(acc[mf][nf][half * 2] * sc,
                             acc[mf][nf][half * 2 + 1] * sc);
                }
            }
    } else {
#pragma unroll
        for (int mf = 0; mf < 4; mf++)
#pragma unroll
            for (int nf = 0; nf < 8; nf++) {
                int n = colBase + nf * 8;
#pragma unroll
                for (int half = 0; half < 2; half++) {
                    int m = rowBase + mf * 16 + half * 8;
                    *(float2*)(Cf + (size_t)m * NHID + n) =
                        make_float2(acc[mf][nf][half * 2], acc[mf][nf][half * 2 + 1]);
                }
            }
    }
}

// ===========================================================================
// Flash attention: Q/K/V all single fp16 -> 1-term QK, 1-term PV.
// Softmax in log2 domain, exp via ex2.approx.f16x2, l via ones-MMA.
// CTA = (b,h) x 128 q-rows, 8 warps, K-tile 128, cp.async double-buffered.
// ===========================================================================
#define KT 128
#define ALDS 72
#define ABUF (128 * 144)           // 18432
#define ASTG (2 * ABUF)            // K, V
#define OQ 0
#define OST ABUF                   // 18432
#define OMSK (OST + 2 * ASTG)      // 92160
#define ATTN_SMEM (OMSK + 1024)

__global__ __launch_bounds__(256, 1)
void attn_tc_kernel(const float* __restrict__ mask)
{
    extern __shared__ char smc[];
    const uint32_t sb = smem_to_u32(smc);

    const int t    = threadIdx.x;
    const int lane = t & 31;
    const int w    = t >> 5;

    const int bh = blockIdx.y;
    const int b  = bh >> 4;
    const int h  = bh & 15;
    const int q0 = blockIdx.x << 7;

    const int rA = lane & 15;
    const int cA = (lane >> 4) << 3;
    const int rB = (lane & 7) + ((lane >> 4) << 3);
    const int cB = lane & 8;
    const int c0 = (lane & 3) << 1;

    const size_t qbase  = ((size_t)bh * NS + q0) * DHEAD;
    const size_t kvbase = (size_t)bh * NS * DHEAD;

    auto issue_kv = [&](int kt, int stg) {
        const size_t base = kvbase + (size_t)kt * KT * DHEAD;
        const uint32_t st = sb + OST + stg * ASTG;
#pragma unroll
        for (int j = 0; j < 4; j++) {
            int idx = t + (j << 8);
            int row = idx >> 3, ch = idx & 7;
            uint32_t so = (uint32_t)(row * 144 + ch * 16);
            size_t go = base + row * DHEAD + ch * 8;
            cp_async16(st + so, g_k16 + go);
            cp_async16(st + ABUF + so, g_v16 + go);
        }
        if (t < 32)
            cp_async16(sb + OMSK + stg * 512 + t * 16,
                       mask + (size_t)b * NS + kt * KT + t * 4);
        cp_commit();
    };

    // prologue: Q tile (single fp16) + KV stage 0
#pragma unroll
    for (int j = 0; j < 4; j++) {
        int idx = t + (j << 8);
        int row = idx >> 3, ch = idx & 7;
        uint32_t so = (uint32_t)(row * 144 + ch * 16);
        cp_async16(sb + OQ + so, g_q16 + qbase + row * DHEAD + ch * 8);
    }
    issue_kv(0, 0);

    float accs[16][4];
    uint32_t pp[16][2];
    float acco[8][4];
    float acco_l[4] = {0.f, 0.f, 0.f, 0.f};
    float m0 = -INFINITY, m1 = -INFINITY;
#pragma unroll
    for (int nf = 0; nf < 8; nf++)
#pragma unroll
        for (int r = 0; r < 4; r++) acco[nf][r] = 0.f;

    const uint32_t bones[2] = {0x3C003C00u, 0x3C003C00u};

    for (int kt = 0; kt < NS / KT; kt++) {
        cp_wait<0>();
        __syncthreads();
        if (kt + 1 < NS / KT) issue_kv(kt + 1, (kt + 1) & 1);

        const int stg = kt & 1;
        const uint32_t st = sb + OST + stg * ASTG;
        const float* msk = (const float*)(smc + OMSK + stg * 512);

        // ---- S = Q K^T (1-term fp16) ----
#pragma unroll
        for (int nf = 0; nf < 16; nf++)
#pragma unroll
            for (int r = 0; r < 4; r++) accs[nf][r] = 0.f;

#pragma unroll
        for (int ks = 0; ks < 4; ks++) {
            uint32_t aq[4];
            uint32_t qo = (uint32_t)((w * 16 + rA) * ALDS + ks * 16 + cA) * 2;
            ldmatrix_x4(aq[0], aq[1], aq[2], aq[3], sb + OQ + qo);
#pragma unroll
            for (int p = 0; p < 8; p++) {
                uint32_t ko = (uint32_t)((p * 16 + rB) * ALDS + ks * 16 + cB) * 2;
                uint32_t h0, h1, h2, h3;
                ldmatrix_x4(h0, h1, h2, h3, st + ko);
                uint32_t bk0[2] = {h0, h1}, bk1[2] = {h2, h3};
                mma_f16(accs[2 * p],     aq, bk0);
                mma_f16(accs[2 * p + 1], aq, bk1);
            }
        }

        // ---- + mask*log2e ----
#pragma unroll
        for (int nf = 0; nf < 16; nf++) {
            float mk0 = msk[nf * 8 + c0];
            float mk1 = msk[nf * 8 + c0 + 1];
            accs[nf][0] = fmaf(mk0, L2E, accs[nf][0]);
            accs[nf][1] = fmaf(mk1, L2E, accs[nf][1]);
            accs[nf][2] = fmaf(mk0, L2E, accs[nf][2]);
            accs[nf][3] = fmaf(mk1, L2E, accs[nf][3]);
        }

        // ---- online softmax (log2 domain) ----
        float tm0 = -INFINITY, tm1 = -INFINITY;
#pragma unroll
        for (int nf = 0; nf < 16; nf++) {
            tm0 = fmaxf(tm0, fmaxf(accs[nf][0], accs[nf][1]));
            tm1 = fmaxf(tm1, fmaxf(accs[nf][2], accs[nf][3]));
        }
        tm0 = fmaxf(tm0, __shfl_xor_sync(0xffffffffu, tm0, 1));
        tm0 = fmaxf(tm0, __shfl_xor_sync(0xffffffffu, tm0, 2));
        tm1 = fmaxf(tm1, __shfl_xor_sync(0xffffffffu, tm1, 1));
        tm1 = fmaxf(tm1, __shfl_xor_sync(0xffffffffu, tm1, 2));

        float mn0 = fmaxf(m0, tm0), mn1 = fmaxf(m1, tm1);
        float cr0 = ex2f(m0 - mn0), cr1 = ex2f(m1 - mn1);
        m0 = mn0; m1 = mn1;

        // ---- P = 2^(S-m) via packed fp16x2 exp ----
#pragma unroll
        for (int nf = 0; nf < 16; nf++) {
            pp[nf][0] = ex2h2(f2h2(accs[nf][0] - mn0, accs[nf][1] - mn0));
            pp[nf][1] = ex2h2(f2h2(accs[nf][2] - mn1, accs[nf][3] - mn1));
        }

#pragma unroll
        for (int nf = 0; nf < 8; nf++) {
            acco[nf][0] *= cr0; acco[nf][1] *= cr0;
            acco[nf][2] *= cr1; acco[nf][3] *= cr1;
        }
        acco_l[0] *= cr0;
        acco_l[2] *= cr1;

        // ---- O += P V ----
#pragma unroll
        for (int kc = 0; kc < 8; kc++) {
            uint32_t aph[4] = { pp[2 * kc][0], pp[2 * kc][1],
                                pp[2 * kc + 1][0], pp[2 * kc + 1][1] };
            mma_f16(acco_l, aph, bones);
#pragma unroll
            for (int pv = 0; pv < 4; pv++) {
                uint32_t vo = (uint32_t)((kc * 16 + rA) * ALDS + pv * 16 + cA) * 2;
                uint32_t h0, h1, h2, h3;
                ldmatrix_x4_trans(h0, h1, h2, h3, st + ABUF + vo);
                uint32_t bv0[2] = {h0, h1}, bv1[2] = {h2, h3};
                mma_f16(acco[2 * pv],     aph, bv0);
                mma_f16(acco[2 * pv + 1], aph, bv1);
            }
        }
    }

    // ---- epilogue: single-fp16 output ----
    float inv0 = 1.f / acco_l[0];
    float inv1 = 1.f / acco_l[2];
    int row0 = q0 + w * 16 + (lane >> 2);
#pragma unroll
    for (int nf = 0; nf < 8; nf++) {
        int d = nf * 8 + c0;
        size_t i0 = ((size_t)(b * NS) + row0) * NHID + h * DHEAD + d;
        size_t i1 = i0 + (size_t)8 * NHID;
        *(uint32_t*)(g_a16 + i0) = f2h2(acco[nf][0] * inv0, acco[nf][1] * inv0);
        *(uint32_t*)(g_a16 + i1) = f2h2(acco[nf][2] * inv1, acco[nf][3] * inv1);
    }
}

// ---------------------------------------------------------------------------
// Launch
// ---------------------------------------------------------------------------
extern "C" void kernel_launch(void* const* d_in, const int* in_sizes, int n_in,
                              void* d_out, int out_size)
{
    const float* X    = (const float*)d_in[0];
    const float* mask = (const float*)d_in[1];
    const float* Wq   = (const float*)d_in[2];
    const float* Wk   = (const float*)d_in[3];
    const float* Wv   = (const float*)d_in[4];
    const float* Wo   = (const float*)d_in[5];
    float* out = (float*)d_out;

    __half *x16, *wh16, *wl16, *wo16h, *wo16l, *a16;
    cudaGetSymbolAddress((void**)&x16,   g_x16);
    cudaGetSymbolAddress((void**)&wh16,  g_wh16);
    cudaGetSymbolAddress((void**)&wl16,  g_wl16);
    cudaGetSymbolAddress((void**)&wo16h, g_wo16h);
    cudaGetSymbolAddress((void**)&wo16l, g_wo16l);
    cudaGetSymbolAddress((void**)&a16,   g_a16);

    cudaFuncSetAttribute(gemm_f16_kernel,
                         cudaFuncAttributeMaxDynamicSharedMemorySize, GEMM_SMEM);
    cudaFuncSetAttribute(attn_tc_kernel,
                         cudaFuncAttributeMaxDynamicSharedMemorySize, ATTN_SMEM);

    int n4x = MTOT * NHID / 4;
    int n4w = NHID * NHID / 4;
    cvt_f16_kernel<<<n4x / 256, 256>>>(X, x16, n4x);
    split_f16_kernel<<<n4w / 256, 256>>>(Wq, wh16,               wl16,               n4w);
    split_f16_kernel<<<n4w / 256, 256>>>(Wk, wh16 + NHID*NHID,   wl16 + NHID*NHID,   n4w);
    split_f16_kernel<<<n4w / 256, 256>>>(Wv, wh16 + 2*NHID*NHID, wl16 + 2*NHID*NHID, n4w);
    split_f16_kernel<<<n4w / 256, 256>>>(Wo, wo16h, wo16l, n4w);

    // fused QKV GEMM
    dim3 gq(3 * NHID / 256, MTOT / 128);   // 12 x 64
    gemm_f16_kernel<<<gq, 256, GEMM_SMEM>>>(x16, wh16, wl16, nullptr, 1);

    // attention
    dim3 ga(NS / KT, NB * NHEADS);         // 16 x 64
    attn_tc_kernel<<<ga, 256, ATTN_SMEM>>>(mask);

    // output projection
    dim3 go(NHID / 256, MTOT / 128);       // 4 x 64
    gemm_f16_kernel<<<go, 256, GEMM_SMEM>>>(a16, wo16h, wo16l, out, 0);
}

// round 15
// speedup vs baseline: 1.7943x; 1.2474x over previous
#include <cuda_runtime.h>
#include <cuda_bf16.h>
#include <cuda_fp16.h>
#include <cstdint>
#include <math.h>

#define NB 4
#define NS 2048
#define NHID 1024
#define NHEADS 16
#define DHEAD 64
#define MTOT (NB * NS)   // 8192

// ---------------------------------------------------------------------------
// Global scratch
// ---------------------------------------------------------------------------
__device__ __half g_x16[MTOT * NHID];                         // X single fp16
__device__ __half g_w16[3 * NHID * NHID];                     // Wq|Wk|Wv single fp16
__device__ __half g_wo16h[NHID * NHID], g_wo16l[NHID * NHID]; // Wo fp16 hi/lo
__device__ __half g_q16[NB * NHEADS * NS * DHEAD];            // Q fp16 (pre-scaled)
__device__ __half g_k16[NB * NHEADS * NS * DHEAD];            // K fp16
__device__ __half g_v16[NB * NHEADS * NS * DHEAD];            // V fp16
__device__ __half g_a16[MTOT * NHID];                         // attn out fp16

// ===========================================================================
// Helpers
// ===========================================================================
__device__ __forceinline__ uint32_t smem_to_u32(const void* p) {
    uint32_t a;
    asm("{ .reg .u64 t; cvta.to.shared.u64 t, %1; cvt.u32.u64 %0, t; }"
        : "=r"(a) : "l"(p));
    return a;
}
__device__ __forceinline__ void cp_async16(uint32_t s, const void* g) {
    asm volatile("cp.async.cg.shared.global [%0], [%1], 16;" :: "r"(s), "l"(g));
}
__device__ __forceinline__ void cp_commit() {
    asm volatile("cp.async.commit_group;" ::: "memory");
}
template <int N>
__device__ __forceinline__ void cp_wait() {
    asm volatile("cp.async.wait_group %0;" :: "n"(N) : "memory");
}
__device__ __forceinline__ void ldmatrix_x4(uint32_t& d0, uint32_t& d1,
                                            uint32_t& d2, uint32_t& d3,
                                            uint32_t addr) {
    asm volatile("ldmatrix.sync.aligned.m8n8.x4.shared.b16 {%0,%1,%2,%3}, [%4];"
        : "=r"(d0), "=r"(d1), "=r"(d2), "=r"(d3) : "r"(addr));
}
__device__ __forceinline__ void ldmatrix_x4_trans(uint32_t& d0, uint32_t& d1,
                                                  uint32_t& d2, uint32_t& d3,
                                                  uint32_t addr) {
    asm volatile("ldmatrix.sync.aligned.m8n8.x4.trans.shared.b16 {%0,%1,%2,%3}, [%4];"
        : "=r"(d0), "=r"(d1), "=r"(d2), "=r"(d3) : "r"(addr));
}
__device__ __forceinline__ void mma_f16(float* c, const uint32_t* a,
                                        const uint32_t* b) {
    asm volatile(
        "mma.sync.aligned.m16n8k16.row.col.f32.f16.f16.f32 "
        "{%0,%1,%2,%3}, {%4,%5,%6,%7}, {%8,%9}, {%0,%1,%2,%3};"
        : "+f"(c[0]), "+f"(c[1]), "+f"(c[2]), "+f"(c[3])
        : "r"(a[0]), "r"(a[1]), "r"(a[2]), "r"(a[3]), "r"(b[0]), "r"(b[1]));
}
__device__ __forceinline__ void split2h(float x, float y,
                                        uint32_t& hi, uint32_t& lo) {
    __half hx = __float2half_rn(x);
    __half hy = __float2half_rn(y);
    __half2 p;
    p.x = hx; p.y = hy; hi = *reinterpret_cast<uint32_t*>(&p);
    p.x = __float2half_rn(x - __half2float(hx));
    p.y = __float2half_rn(y - __half2float(hy));
    lo = *reinterpret_cast<uint32_t*>(&p);
}
__device__ __forceinline__ uint32_t f2h2(float x, float y) {
    uint32_t r;
    asm("cvt.rn.f16x2.f32 %0, %1, %2;" : "=r"(r) : "f"(y), "f"(x));
    return r;
}
__device__ __forceinline__ float ex2f(float x) {
    float r;
    asm("ex2.approx.f32 %0, %1;" : "=f"(r) : "f"(x));
    return r;
}
__device__ __forceinline__ uint32_t ex2h2(uint32_t x) {
    uint32_t r;
    asm("ex2.approx.f16x2 %0, %1;" : "=r"(r) : "r"(x));
    return r;
}

#define L2E 1.4426950408889634f

// ===========================================================================
// Conversion kernels
// ===========================================================================
__global__ __launch_bounds__(256)
void cvt_f16_kernel(const float* __restrict__ src,
                    __half* __restrict__ h, int n4)
{
    int i = blockIdx.x * 256 + threadIdx.x;
    if (i < n4) {
        float4 v = ((const float4*)src)[i];
        uint2 o;
        o.x = f2h2(v.x, v.y);
        o.y = f2h2(v.z, v.w);
        ((uint2*)h)[i] = o;
    }
}

__global__ __launch_bounds__(256)
void split_f16_kernel(const float* __restrict__ src,
                      __half* __restrict__ h,
                      __half* __restrict__ l, int n4)
{
    int i = blockIdx.x * 256 + threadIdx.x;
    if (i < n4) {
        float4 v = ((const float4*)src)[i];
        uint2 hi, lo;
        split2h(v.x, v.y, hi.x, lo.x);
        split2h(v.z, v.w, hi.y, lo.y);
        ((uint2*)h)[i] = hi;
        ((uint2*)l)[i] = lo;
    }
}

// ===========================================================================
// QKV GEMM (fp16 1-term): D = X * W.  X fp16, W single fp16.
// CTA 128x256, warp 64x64, BK=32, 3 stages.
// Scatters Q (fp16, pre-scaled 0.125*log2e), K (fp16), V (fp16) into [B,NH,S,HD].
// ===========================================================================
#define GLDS 40
#define GA_BUF 10240           // 128 rows x 80B
#define GB_BUF 20480           // 256 rows x 80B
#define Q1STAGE (GA_BUF + GB_BUF)          // 30720
#define QKV_SMEM (3 * Q1STAGE)             // 92160

__global__ __launch_bounds__(256, 1)
void gemm_qkv1_kernel(const __half* __restrict__ A,
                      const __half* __restrict__ B)
{
    extern __shared__ char smc[];
    const uint32_t sb = smem_to_u32(smc);

    const int t    = threadIdx.x;
    const int lane = t & 31;
    const int wid  = t >> 5;
    const int wm   = wid & 1;
    const int wn   = wid >> 1;
    const int m0   = blockIdx.y << 7;
    const int n0   = blockIdx.x << 8;

    const int rA = lane & 15;
    const int cA = (lane >> 4) << 3;
    const int rB = (lane & 7) + ((lane >> 4) << 3);
    const int cB = lane & 8;

    auto issue = [&](int c, int stg) {
        const int k0 = c << 5;
        const uint32_t st = sb + stg * Q1STAGE;
#pragma unroll
        for (int j = 0; j < 2; j++) {
            int idx = t + (j << 8);
            int row = idx >> 2, ch = idx & 3;
            uint32_t so = (uint32_t)(row * 80 + ch * 16);
            cp_async16(st + so, A + (size_t)(m0 + row) * NHID + k0 + ch * 8);
        }
#pragma unroll
        for (int j = 0; j < 4; j++) {
            int idx = t + (j << 8);
            int row = idx >> 2, ch = idx & 3;
            uint32_t so = (uint32_t)(row * 80 + ch * 16);
            cp_async16(st + GA_BUF + so, B + (size_t)(n0 + row) * NHID + k0 + ch * 8);
        }
        cp_commit();
    };

    float acc[4][8][4];
#pragma unroll
    for (int mf = 0; mf < 4; mf++)
#pragma unroll
        for (int nf = 0; nf < 8; nf++)
#pragma unroll
            for (int r = 0; r < 4; r++) acc[mf][nf][r] = 0.f;

    issue(0, 0);
    issue(1, 1);

    for (int c = 0; c < 32; ++c) {
        if (c < 31) cp_wait<1>(); else cp_wait<0>();
        __syncthreads();
        if (c + 2 < 32) issue(c + 2, (c + 2) % 3);

        const uint32_t st = sb + (c % 3) * Q1STAGE;
#pragma unroll
        for (int ks = 0; ks < 2; ks++) {
            const int k0 = ks << 4;
            uint32_t a[4][4];
#pragma unroll
            for (int mf = 0; mf < 4; mf++) {
                uint32_t ro = (uint32_t)((wm * 64 + mf * 16 + rA) * GLDS + k0 + cA) * 2;
                ldmatrix_x4(a[mf][0], a[mf][1], a[mf][2], a[mf][3], st + ro);
            }
#pragma unroll
            for (int p = 0; p < 4; p++) {
                uint32_t ro = (uint32_t)((wn * 64 + p * 16 + rB) * GLDS + k0 + cB) * 2;
                uint32_t h0, h1, h2, h3;
                ldmatrix_x4(h0, h1, h2, h3, st + GA_BUF + ro);
                uint32_t b0[2] = {h0, h1}, b1[2] = {h2, h3};
#pragma unroll
                for (int mf = 0; mf < 4; mf++) {
                    mma_f16(acc[mf][2 * p],     a[mf], b0);
                    mma_f16(acc[mf][2 * p + 1], a[mf], b1);
                }
            }
        }
    }

    const int rowBase = m0 + wm * 64 + (lane >> 2);
    const int colBase = n0 + wn * 64 + ((lane & 3) << 1);
    const int which = n0 >> 10;     // 0=Q 1=K 2=V
    const float sc = (which == 0) ? 0.125f * L2E : 1.0f;
    __half* dst = (which == 0) ? g_q16 : (which == 1) ? g_k16 : g_v16;

#pragma unroll
    for (int mf = 0; mf < 4; mf++)
#pragma unroll
        for (int nf = 0; nf < 8; nf++) {
            int n = colBase + nf * 8;
            int r = n & 1023;
            int h = r >> 6, d = r & 63;
#pragma unroll
            for (int half = 0; half < 2; half++) {
                int m = rowBase + mf * 16 + half * 8;
                int b = m >> 11, s = m & (NS - 1);
                size_t idx = ((((size_t)(b * NHEADS + h)) * NS + s) << 6) + d;
                *(uint32_t*)(dst + idx) =
                    f2h2(acc[mf][nf][half * 2] * sc,
                         acc[mf][nf][half * 2 + 1] * sc);
            }
        }
}

// ===========================================================================
// Output GEMM (fp16 2-term, unchanged): out = A*Woh + A*Wol -> fp32
// ===========================================================================
#define O2STAGE (GA_BUF + 2 * GB_BUF)      // 51200
#define OUT_SMEM (3 * O2STAGE)             // 153600

__global__ __launch_bounds__(256, 1)
void gemm_out_kernel(const __half* __restrict__ A,
                     const __half* __restrict__ Bh,
                     const __half* __restrict__ Bl,
                     float* __restrict__ Cf)
{
    extern __shared__ char smc[];
    const uint32_t sb = smem_to_u32(smc);

    const int t    = threadIdx.x;
    const int lane = t & 31;
    const int wid  = t >> 5;
    const int wm   = wid & 1;
    const int wn   = wid >> 1;
    const int m0   = blockIdx.y << 7;
    const int n0   = blockIdx.x << 8;

    const int rA = lane & 15;
    const int cA = (lane >> 4) << 3;
    const int rB = (lane & 7) + ((lane >> 4) << 3);
    const int cB = lane & 8;

    auto issue = [&](int c, int stg) {
        const int k0 = c << 5;
        const uint32_t st = sb + stg * O2STAGE;
#pragma unroll
        for (int j = 0; j < 2; j++) {
            int idx = t + (j << 8);
            int row = idx >> 2, ch = idx & 3;
            uint32_t so = (uint32_t)(row * 80 + ch * 16);
            cp_async16(st + so, A + (size_t)(m0 + row) * NHID + k0 + ch * 8);
        }
#pragma unroll
        for (int j = 0; j < 4; j++) {
            int idx = t + (j << 8);
            int row = idx >> 2, ch = idx & 3;
            uint32_t so = (uint32_t)(row * 80 + ch * 16);
            const size_t go = (size_t)(n0 + row) * NHID + k0 + ch * 8;
            cp_async16(st + GA_BUF + so, Bh + go);
            cp_async16(st + GA_BUF + GB_BUF + so, Bl + go);
        }
        cp_commit();
    };

    float acc[4][8][4];
#pragma unroll
    for (int mf = 0; mf < 4; mf++)
#pragma unroll
        for (int nf = 0; nf < 8; nf++)
#pragma unroll
            for (int r = 0; r < 4; r++) acc[mf][nf][r] = 0.f;

    issue(0, 0);
    issue(1, 1);

    for (int c = 0; c < 32; ++c) {
        if (c < 31) cp_wait<1>(); else cp_wait<0>();
        __syncthreads();
        if (c + 2 < 32) issue(c + 2, (c + 2) % 3);

        const uint32_t st = sb + (c % 3) * O2STAGE;
#pragma unroll
        for (int ks = 0; ks < 2; ks++) {
            const int k0 = ks << 4;
            uint32_t a[4][4];
#pragma unroll
            for (int mf = 0; mf < 4; mf++) {
                uint32_t ro = (uint32_t)((wm * 64 + mf * 16 + rA) * GLDS + k0 + cA) * 2;
                ldmatrix_x4(a[mf][0], a[mf][1], a[mf][2], a[mf][3], st + ro);
            }
#pragma unroll
            for (int p = 0; p < 4; p++) {
                uint32_t ro = (uint32_t)((wn * 64 + p * 16 + rB) * GLDS + k0 + cB) * 2;
                uint32_t h0, h1, h2, h3, e0, e1, e2, e3;
                ldmatrix_x4(h0, h1, h2, h3, st + GA_BUF + ro);
                ldmatrix_x4(e0, e1, e2, e3, st + GA_BUF + GB_BUF + ro);
                uint32_t bh0[2] = {h0, h1}, bh1[2] = {h2, h3};
                uint32_t bl0[2] = {e0, e1}, bl1[2] = {e2, e3};
#pragma unroll
                for (int mf = 0; mf < 4; mf++) {
                    mma_f16(acc[mf][2 * p],     a[mf], bh0);
                    mma_f16(acc[mf][2 * p],     a[mf], bl0);
                    mma_f16(acc[mf][2 * p + 1], a[mf], bh1);
                    mma_f16(acc[mf][2 * p + 1], a[mf], bl1);
                }
            }
        }
    }

    const int rowBase = m0 + wm * 64 + (lane >> 2);
    const int colBase = n0 + wn * 64 + ((lane & 3) << 1);
#pragma unroll
    for (int mf = 0; mf < 4; mf++)
#pragma unroll
        for (int nf = 0; nf < 8; nf++) {
            int n = colBase + nf * 8;
#pragma unroll
            for (int half = 0; half < 2; half++) {
                int m = rowBase + mf * 16 + half * 8;
                *(float2*)(Cf + (size_t)m * NHID + n) =
                    make_float2(acc[mf][nf][half * 2], acc[mf][nf][half * 2 + 1]);
            }
        }
}

// ===========================================================================
// Flash attention (round-14, unchanged): Q/K/V fp16 1-term, log2 softmax,
// ex2.f16x2, l via ones-MMA. CTA = (b,h) x 128 q-rows, K-tile 128.
// ===========================================================================
#define KT 128
#define ALDS 72
#define ABUF (128 * 144)
#define ASTG (2 * ABUF)
#define OQ 0
#define OST ABUF
#define OMSK (OST + 2 * ASTG)
#define ATTN_SMEM (OMSK + 1024)

__global__ __launch_bounds__(256, 1)
void attn_tc_kernel(const float* __restrict__ mask)
{
    extern __shared__ char smc[];
    const uint32_t sb = smem_to_u32(smc);

    const int t    = threadIdx.x;
    const int lane = t & 31;
    const int w    = t >> 5;

    const int bh = blockIdx.y;
    const int b  = bh >> 4;
    const int h  = bh & 15;
    const int q0 = blockIdx.x << 7;

    const int rA = lane & 15;
    const int cA = (lane >> 4) << 3;
    const int rB = (lane & 7) + ((lane >> 4) << 3);
    const int cB = lane & 8;
    const int c0 = (lane & 3) << 1;

    const size_t qbase  = ((size_t)bh * NS + q0) * DHEAD;
    const size_t kvbase = (size_t)bh * NS * DHEAD;

    auto issue_kv = [&](int kt, int stg) {
        const size_t base = kvbase + (size_t)kt * KT * DHEAD;
        const uint32_t st = sb + OST + stg * ASTG;
#pragma unroll
        for (int j = 0; j < 4; j++) {
            int idx = t + (j << 8);
            int row = idx >> 3, ch = idx & 7;
            uint32_t so = (uint32_t)(row * 144 + ch * 16);
            size_t go = base + row * DHEAD + ch * 8;
            cp_async16(st + so, g_k16 + go);
            cp_async16(st + ABUF + so, g_v16 + go);
        }
        if (t < 32)
            cp_async16(sb + OMSK + stg * 512 + t * 16,
                       mask + (size_t)b * NS + kt * KT + t * 4);
        cp_commit();
    };

#pragma unroll
    for (int j = 0; j < 4; j++) {
        int idx = t + (j << 8);
        int row = idx >> 3, ch = idx & 7;
        uint32_t so = (uint32_t)(row * 144 + ch * 16);
        cp_async16(sb + OQ + so, g_q16 + qbase + row * DHEAD + ch * 8);
    }
    issue_kv(0, 0);

    float accs[16][4];
    uint32_t pp[16][2];
    float acco[8][4];
    float acco_l[4] = {0.f, 0.f, 0.f, 0.f};
    float m0 = -INFINITY, m1 = -INFINITY;
#pragma unroll
    for (int nf = 0; nf < 8; nf++)
#pragma unroll
        for (int r = 0; r < 4; r++) acco[nf][r] = 0.f;

    const uint32_t bones[2] = {0x3C003C00u, 0x3C003C00u};

    for (int kt = 0; kt < NS / KT; kt++) {
        cp_wait<0>();
        __syncthreads();
        if (kt + 1 < NS / KT) issue_kv(kt + 1, (kt + 1) & 1);

        const int stg = kt & 1;
        const uint32_t st = sb + OST + stg * ASTG;
        const float* msk = (const float*)(smc + OMSK + stg * 512);

#pragma unroll
        for (int nf = 0; nf < 16; nf++)
#pragma unroll
            for (int r = 0; r < 4; r++) accs[nf][r] = 0.f;

#pragma unroll
        for (int ks = 0; ks < 4; ks++) {
            uint32_t aq[4];
            uint32_t qo = (uint32_t)((w * 16 + rA) * ALDS + ks * 16 + cA) * 2;
            ldmatrix_x4(aq[0], aq[1], aq[2], aq[3], sb + OQ + qo);
#pragma unroll
            for (int p = 0; p < 8; p++) {
                uint32_t ko = (uint32_t)((p * 16 + rB) * ALDS + ks * 16 + cB) * 2;
                uint32_t h0, h1, h2, h3;
                ldmatrix_x4(h0, h1, h2, h3, st + ko);
                uint32_t bk0[2] = {h0, h1}, bk1[2] = {h2, h3};
                mma_f16(accs[2 * p],     aq, bk0);
                mma_f16(accs[2 * p + 1], aq, bk1);
            }
        }

#pragma unroll
        for (int nf = 0; nf < 16; nf++) {
            float mk0 = msk[nf * 8 + c0];
            float mk1 = msk[nf * 8 + c0 + 1];
            accs[nf][0] = fmaf(mk0, L2E, accs[nf][0]);
            accs[nf][1] = fmaf(mk1, L2E, accs[nf][1]);
            accs[nf][2] = fmaf(mk0, L2E, accs[nf][2]);
            accs[nf][3] = fmaf(mk1, L2E, accs[nf][3]);
        }

        float tm0 = -INFINITY, tm1 = -INFINITY;
#pragma unroll
        for (int nf = 0; nf < 16; nf++) {
            tm0 = fmaxf(tm0, fmaxf(accs[nf][0], accs[nf][1]));
            tm1 = fmaxf(tm1, fmaxf(accs[nf][2], accs[nf][3]));
        }
        tm0 = fmaxf(tm0, __shfl_xor_sync(0xffffffffu, tm0, 1));
        tm0 = fmaxf(tm0, __shfl_xor_sync(0xffffffffu, tm0, 2));
        tm1 = fmaxf(tm1, __shfl_xor_sync(0xffffffffu, tm1, 1));
        tm1 = fmaxf(tm1, __shfl_xor_sync(0xffffffffu, tm1, 2));

        float mn0 = fmaxf(m0, tm0), mn1 = fmaxf(m1, tm1);
        float cr0 = ex2f(m0 - mn0), cr1 = ex2f(m1 - mn1);
        m0 = mn0; m1 = mn1;

#pragma unroll
        for (int nf = 0; nf < 16; nf++) {
            pp[nf][0] = ex2h2(f2h2(accs[nf][0] - mn0, accs[nf][1] - mn0));
            pp[nf][1] = ex2h2(f2h2(accs[nf][2] - mn1, accs[nf][3] - mn1));
        }

#pragma unroll
        for (int nf = 0; nf < 8; nf++) {
            acco[nf][0] *= cr0; acco[nf][1] *= cr0;
            acco[nf][2] *= cr1; acco[nf][3] *= cr1;
        }
        acco_l[0] *= cr0;
        acco_l[2] *= cr1;

#pragma unroll
        for (int kc = 0; kc < 8; kc++) {
            uint32_t aph[4] = { pp[2 * kc][0], pp[2 * kc][1],
                                pp[2 * kc + 1][0], pp[2 * kc + 1][1] };
            mma_f16(acco_l, aph, bones);
#pragma unroll
            for (int pv = 0; pv < 4; pv++) {
                uint32_t vo = (uint32_t)((kc * 16 + rA) * ALDS + pv * 16 + cA) * 2;
                uint32_t h0, h1, h2, h3;
                ldmatrix_x4_trans(h0, h1, h2, h3, st + ABUF + vo);
                uint32_t bv0[2] = {h0, h1}, bv1[2] = {h2, h3};
                mma_f16(acco[2 * pv],     aph, bv0);
                mma_f16(acco[2 * pv + 1], aph, bv1);
            }
        }
    }

    float inv0 = 1.f / acco_l[0];
    float inv1 = 1.f / acco_l[2];
    int row0 = q0 + w * 16 + (lane >> 2);
#pragma unroll
    for (int nf = 0; nf < 8; nf++) {
        int d = nf * 8 + c0;
        size_t i0 = ((size_t)(b * NS) + row0) * NHID + h * DHEAD + d;
        size_t i1 = i0 + (size_t)8 * NHID;
        *(uint32_t*)(g_a16 + i0) = f2h2(acco[nf][0] * inv0, acco[nf][1] * inv0);
        *(uint32_t*)(g_a16 + i1) = f2h2(acco[nf][2] * inv1, acco[nf][3] * inv1);
    }
}

// ---------------------------------------------------------------------------
// Launch
// ---------------------------------------------------------------------------
extern "C" void kernel_launch(void* const* d_in, const int* in_sizes, int n_in,
                              void* d_out, int out_size)
{
    const float* X    = (const float*)d_in[0];
    const float* mask = (const float*)d_in[1];
    const float* Wq   = (const float*)d_in[2];
    const float* Wk   = (const float*)d_in[3];
    const float* Wv   = (const float*)d_in[4];
    const float* Wo   = (const float*)d_in[5];
    float* out = (float*)d_out;

    __half *x16, *w16, *wo16h, *wo16l, *a16;
    cudaGetSymbolAddress((void**)&x16,   g_x16);
    cudaGetSymbolAddress((void**)&w16,   g_w16);
    cudaGetSymbolAddress((void**)&wo16h, g_wo16h);
    cudaGetSymbolAddress((void**)&wo16l, g_wo16l);
    cudaGetSymbolAddress((void**)&a16,   g_a16);

    cudaFuncSetAttribute(gemm_qkv1_kernel,
                         cudaFuncAttributeMaxDynamicSharedMemorySize, QKV_SMEM);
    cudaFuncSetAttribute(gemm_out_kernel,
                         cudaFuncAttributeMaxDynamicSharedMemorySize, OUT_SMEM);
    cudaFuncSetAttribute(attn_tc_kernel,
                         cudaFuncAttributeMaxDynamicSharedMemorySize, ATTN_SMEM);

    int n4x = MTOT * NHID / 4;
    int n4w = NHID * NHID / 4;
    cvt_f16_kernel<<<n4x / 256, 256>>>(X, x16, n4x);
    cvt_f16_kernel<<<n4w / 256, 256>>>(Wq, w16,                 n4w);
    cvt_f16_kernel<<<n4w / 256, 256>>>(Wk, w16 + NHID*NHID,     n4w);
    cvt_f16_kernel<<<n4w / 256, 256>>>(Wv, w16 + 2*NHID*NHID,   n4w);
    split_f16_kernel<<<n4w / 256, 256>>>(Wo, wo16h, wo16l, n4w);

    // fused QKV GEMM (1-term)
    dim3 gq(3 * NHID / 256, MTOT / 128);   // 12 x 64
    gemm_qkv1_kernel<<<gq, 256, QKV_SMEM>>>(x16, w16);

    // attention
    dim3 ga(NS / KT, NB * NHEADS);         // 16 x 64
    attn_tc_kernel<<<ga, 256, ATTN_SMEM>>>(mask);

    // output projection (2-term)
    dim3 go(NHID / 256, MTOT / 128);       // 4 x 64
    gemm_out_kernel<<<go, 256, OUT_SMEM>>>(a16, wo16h, wo16l, out);
}

// round 16
// speedup vs baseline: 1.9702x; 1.0981x over previous
#include <cuda_runtime.h>
#include <cuda_bf16.h>
#include <cuda_fp16.h>
#include <cstdint>
#include <math.h>

#define NB 4
#define NS 2048
#define NHID 1024
#define NHEADS 16
#define DHEAD 64
#define MTOT (NB * NS)   // 8192

// ---------------------------------------------------------------------------
// Global scratch
// ---------------------------------------------------------------------------
__device__ __half g_x16[MTOT * NHID];               // X fp16
__device__ __half g_w16[3 * NHID * NHID];           // Wq|Wk|Wv fp16
__device__ __half g_wo16[NHID * NHID];              // Wo fp16
__device__ __half g_q16[NB * NHEADS * NS * DHEAD];  // Q fp16 (pre-scaled)
__device__ __half g_k16[NB * NHEADS * NS * DHEAD];  // K fp16
__device__ __half g_v16[NB * NHEADS * NS * DHEAD];  // V fp16
__device__ __half g_a16[MTOT * NHID];               // attn out fp16

// ===========================================================================
// Helpers
// ===========================================================================
__device__ __forceinline__ uint32_t smem_to_u32(const void* p) {
    uint32_t a;
    asm("{ .reg .u64 t; cvta.to.shared.u64 t, %1; cvt.u32.u64 %0, t; }"
        : "=r"(a) : "l"(p));
    return a;
}
__device__ __forceinline__ void cp_async16(uint32_t s, const void* g) {
    asm volatile("cp.async.cg.shared.global [%0], [%1], 16;" :: "r"(s), "l"(g));
}
__device__ __forceinline__ void cp_commit() {
    asm volatile("cp.async.commit_group;" ::: "memory");
}
template <int N>
__device__ __forceinline__ void cp_wait() {
    asm volatile("cp.async.wait_group %0;" :: "n"(N) : "memory");
}
__device__ __forceinline__ void ldmatrix_x4(uint32_t& d0, uint32_t& d1,
                                            uint32_t& d2, uint32_t& d3,
                                            uint32_t addr) {
    asm volatile("ldmatrix.sync.aligned.m8n8.x4.shared.b16 {%0,%1,%2,%3}, [%4];"
        : "=r"(d0), "=r"(d1), "=r"(d2), "=r"(d3) : "r"(addr));
}
__device__ __forceinline__ void ldmatrix_x4_trans(uint32_t& d0, uint32_t& d1,
                                                  uint32_t& d2, uint32_t& d3,
                                                  uint32_t addr) {
    asm volatile("ldmatrix.sync.aligned.m8n8.x4.trans.shared.b16 {%0,%1,%2,%3}, [%4];"
        : "=r"(d0), "=r"(d1), "=r"(d2), "=r"(d3) : "r"(addr));
}
__device__ __forceinline__ void mma_f16(float* c, const uint32_t* a,
                                        const uint32_t* b) {
    asm volatile(
        "mma.sync.aligned.m16n8k16.row.col.f32.f16.f16.f32 "
        "{%0,%1,%2,%3}, {%4,%5,%6,%7}, {%8,%9}, {%0,%1,%2,%3};"
        : "+f"(c[0]), "+f"(c[1]), "+f"(c[2]), "+f"(c[3])
        : "r"(a[0]), "r"(a[1]), "r"(a[2]), "r"(a[3]), "r"(b[0]), "r"(b[1]));
}
__device__ __forceinline__ uint32_t f2h2(float x, float y) {
    uint32_t r;
    asm("cvt.rn.f16x2.f32 %0, %1, %2;" : "=r"(r) : "f"(y), "f"(x));
    return r;
}
__device__ __forceinline__ float ex2f(float x) {
    float r;
    asm("ex2.approx.f32 %0, %1;" : "=f"(r) : "f"(x));
    return r;
}
__device__ __forceinline__ uint32_t ex2h2(uint32_t x) {
    uint32_t r;
    asm("ex2.approx.f16x2 %0, %1;" : "=r"(r) : "r"(x));
    return r;
}

#define L2E 1.4426950408889634f

// ===========================================================================
// Conversion kernel: fp32 -> fp16
// ===========================================================================
__global__ __launch_bounds__(256)
void cvt_f16_kernel(const float* __restrict__ src,
                    __half* __restrict__ h, int n4)
{
    int i = blockIdx.x * 256 + threadIdx.x;
    if (i < n4) {
        float4 v = ((const float4*)src)[i];
        uint2 o;
        o.x = f2h2(v.x, v.y);
        o.y = f2h2(v.z, v.w);
        ((uint2*)h)[i] = o;
    }
}

// ===========================================================================
// fp16 1-term GEMM: D = A * B.  CTA 128x256, warp 64x64, BK=32, 3 stages.
// qkvMode=1: scatter Q (fp16, pre-scaled 0.125*log2e), K, V into [B,NH,S,HD].
// qkvMode=0: fp32 out to Cf.
// ===========================================================================
#define GLDS 40
#define GA_BUF 10240           // 128 rows x 80B
#define GB_BUF 20480           // 256 rows x 80B
#define G1STAGE (GA_BUF + GB_BUF)          // 30720
#define GEMM_SMEM (3 * G1STAGE)            // 92160

__global__ __launch_bounds__(256, 1)
void gemm_1t_kernel(const __half* __restrict__ A,
                    const __half* __restrict__ B,
                    float* __restrict__ Cf, int qkvMode)
{
    extern __shared__ char smc[];
    const uint32_t sb = smem_to_u32(smc);

    const int t    = threadIdx.x;
    const int lane = t & 31;
    const int wid  = t >> 5;
    const int wm   = wid & 1;
    const int wn   = wid >> 1;
    const int m0   = blockIdx.y << 7;
    const int n0   = blockIdx.x << 8;

    const int rA = lane & 15;
    const int cA = (lane >> 4) << 3;
    const int rB = (lane & 7) + ((lane >> 4) << 3);
    const int cB = lane & 8;

    auto issue = [&](int c, int stg) {
        const int k0 = c << 5;
        const uint32_t st = sb + stg * G1STAGE;
#pragma unroll
        for (int j = 0; j < 2; j++) {
            int idx = t + (j << 8);
            int row = idx >> 2, ch = idx & 3;
            uint32_t so = (uint32_t)(row * 80 + ch * 16);
            cp_async16(st + so, A + (size_t)(m0 + row) * NHID + k0 + ch * 8);
        }
#pragma unroll
        for (int j = 0; j < 4; j++) {
            int idx = t + (j << 8);
            int row = idx >> 2, ch = idx & 3;
            uint32_t so = (uint32_t)(row * 80 + ch * 16);
            cp_async16(st + GA_BUF + so, B + (size_t)(n0 + row) * NHID + k0 + ch * 8);
        }
        cp_commit();
    };

    float acc[4][8][4];
#pragma unroll
    for (int mf = 0; mf < 4; mf++)
#pragma unroll
        for (int nf = 0; nf < 8; nf++)
#pragma unroll
            for (int r = 0; r < 4; r++) acc[mf][nf][r] = 0.f;

    issue(0, 0);
    issue(1, 1);

    for (int c = 0; c < 32; ++c) {
        if (c < 31) cp_wait<1>(); else cp_wait<0>();
        __syncthreads();
        if (c + 2 < 32) issue(c + 2, (c + 2) % 3);

        const uint32_t st = sb + (c % 3) * G1STAGE;
#pragma unroll
        for (int ks = 0; ks < 2; ks++) {
            const int k0 = ks << 4;
            uint32_t a[4][4];
#pragma unroll
            for (int mf = 0; mf < 4; mf++) {
                uint32_t ro = (uint32_t)((wm * 64 + mf * 16 + rA) * GLDS + k0 + cA) * 2;
                ldmatrix_x4(a[mf][0], a[mf][1], a[mf][2], a[mf][3], st + ro);
            }
#pragma unroll
            for (int p = 0; p < 4; p++) {
                uint32_t ro = (uint32_t)((wn * 64 + p * 16 + rB) * GLDS + k0 + cB) * 2;
                uint32_t h0, h1, h2, h3;
                ldmatrix_x4(h0, h1, h2, h3, st + GA_BUF + ro);
                uint32_t b0[2] = {h0, h1}, b1[2] = {h2, h3};
#pragma unroll
                for (int mf = 0; mf < 4; mf++) {
                    mma_f16(acc[mf][2 * p],     a[mf], b0);
                    mma_f16(acc[mf][2 * p + 1], a[mf], b1);
                }
            }
        }
    }

    const int rowBase = m0 + wm * 64 + (lane >> 2);
    const int colBase = n0 + wn * 64 + ((lane & 3) << 1);

    if (qkvMode) {
        const int which = n0 >> 10;     // 0=Q 1=K 2=V
        const float sc = (which == 0) ? 0.125f * L2E : 1.0f;
        __half* dst = (which == 0) ? g_q16 : (which == 1) ? g_k16 : g_v16;
#pragma unroll
        for (int mf = 0; mf < 4; mf++)
#pragma unroll
            for (int nf = 0; nf < 8; nf++) {
                int n = colBase + nf * 8;
                int r = n & 1023;
                int h = r >> 6, d = r & 63;
#pragma unroll
                for (int half = 0; half < 2; half++) {
                    int m = rowBase + mf * 16 + half * 8;
                    int b = m >> 11, s = m & (NS - 1);
                    size_t idx = ((((size_t)(b * NHEADS + h)) * NS + s) << 6) + d;
                    *(uint32_t*)(dst + idx) =
                        f2h2(acc[mf][nf][half * 2] * sc,
                             acc[mf][nf][half * 2 + 1] * sc);
                }
            }
    } else {
#pragma unroll
        for (int mf = 0; mf < 4; mf++)
#pragma unroll
            for (int nf = 0; nf < 8; nf++) {
                int n = colBase + nf * 8;
#pragma unroll
                for (int half = 0; half < 2; half++) {
                    int m = rowBase + mf * 16 + half * 8;
                    *(float2*)(Cf + (size_t)m * NHID + n) =
                        make_float2(acc[mf][nf][half * 2], acc[mf][nf][half * 2 + 1]);
                }
            }
    }
}

// ===========================================================================
// Flash attention: Q/K/V fp16 1-term; Q fragments cached in registers;
// log2 softmax, ex2.f16x2, l via ones-MMA.
// CTA = (b,h) x 128 q-rows, 8 warps, K-tile 128, cp.async double-buffered.
// ===========================================================================
#define KT 128
#define ALDS 72
#define ABUF (128 * 144)
#define ASTG (2 * ABUF)
#define OQ 0
#define OST ABUF
#define OMSK (OST + 2 * ASTG)
#define ATTN_SMEM (OMSK + 1024)

__global__ __launch_bounds__(256, 1)
void attn_tc_kernel(const float* __restrict__ mask)
{
    extern __shared__ char smc[];
    const uint32_t sb = smem_to_u32(smc);

    const int t    = threadIdx.x;
    const int lane = t & 31;
    const int w    = t >> 5;

    const int bh = blockIdx.y;
    const int b  = bh >> 4;
    const int h  = bh & 15;
    const int q0 = blockIdx.x << 7;

    const int rA = lane & 15;
    const int cA = (lane >> 4) << 3;
    const int rB = (lane & 7) + ((lane >> 4) << 3);
    const int cB = lane & 8;
    const int c0 = (lane & 3) << 1;

    const size_t qbase  = ((size_t)bh * NS + q0) * DHEAD;
    const size_t kvbase = (size_t)bh * NS * DHEAD;

    auto issue_kv = [&](int kt, int stg) {
        const size_t base = kvbase + (size_t)kt * KT * DHEAD;
        const uint32_t st = sb + OST + stg * ASTG;
#pragma unroll
        for (int j = 0; j < 4; j++) {
            int idx = t + (j << 8);
            int row = idx >> 3, ch = idx & 7;
            uint32_t so = (uint32_t)(row * 144 + ch * 16);
            size_t go = base + row * DHEAD + ch * 8;
            cp_async16(st + so, g_k16 + go);
            cp_async16(st + ABUF + so, g_v16 + go);
        }
        if (t < 32)
            cp_async16(sb + OMSK + stg * 512 + t * 16,
                       mask + (size_t)b * NS + kt * KT + t * 4);
        cp_commit();
    };

    // prologue: Q tile + KV stage 0 (one group)
#pragma unroll
    for (int j = 0; j < 4; j++) {
        int idx = t + (j << 8);
        int row = idx >> 3, ch = idx & 7;
        uint32_t so = (uint32_t)(row * 144 + ch * 16);
        cp_async16(sb + OQ + so, g_q16 + qbase + row * DHEAD + ch * 8);
    }
    issue_kv(0, 0);

    // wait for group 0, then cache Q fragments in registers (used every tile)
    cp_wait<0>();
    __syncthreads();
    uint32_t aqr[4][4];
#pragma unroll
    for (int ks = 0; ks < 4; ks++) {
        uint32_t qo = (uint32_t)((w * 16 + rA) * ALDS + ks * 16 + cA) * 2;
        ldmatrix_x4(aqr[ks][0], aqr[ks][1], aqr[ks][2], aqr[ks][3], sb + OQ + qo);
    }

    float accs[16][4];
    uint32_t pp[16][2];
    float acco[8][4];
    float acco_l[4] = {0.f, 0.f, 0.f, 0.f};
    float m0 = -INFINITY, m1 = -INFINITY;
#pragma unroll
    for (int nf = 0; nf < 8; nf++)
#pragma unroll
        for (int r = 0; r < 4; r++) acco[nf][r] = 0.f;

    const uint32_t bones[2] = {0x3C003C00u, 0x3C003C00u};

    for (int kt = 0; kt < NS / KT; kt++) {
        cp_wait<0>();
        __syncthreads();
        if (kt + 1 < NS / KT) issue_kv(kt + 1, (kt + 1) & 1);

        const int stg = kt & 1;
        const uint32_t st = sb + OST + stg * ASTG;
        const float* msk = (const float*)(smc + OMSK + stg * 512);

        // ---- S = Q K^T (Q from registers) ----
#pragma unroll
        for (int nf = 0; nf < 16; nf++)
#pragma unroll
            for (int r = 0; r < 4; r++) accs[nf][r] = 0.f;

#pragma unroll
        for (int ks = 0; ks < 4; ks++) {
#pragma unroll
            for (int p = 0; p < 8; p++) {
                uint32_t ko = (uint32_t)((p * 16 + rB) * ALDS + ks * 16 + cB) * 2;
                uint32_t h0, h1, h2, h3;
                ldmatrix_x4(h0, h1, h2, h3, st + ko);
                uint32_t bk0[2] = {h0, h1}, bk1[2] = {h2, h3};
                mma_f16(accs[2 * p],     aqr[ks], bk0);
                mma_f16(accs[2 * p + 1], aqr[ks], bk1);
            }
        }

        // ---- + mask*log2e ----
#pragma unroll
        for (int nf = 0; nf < 16; nf++) {
            float mk0 = msk[nf * 8 + c0];
            float mk1 = msk[nf * 8 + c0 + 1];
            accs[nf][0] = fmaf(mk0, L2E, accs[nf][0]);
            accs[nf][1] = fmaf(mk1, L2E, accs[nf][1]);
            accs[nf][2] = fmaf(mk0, L2E, accs[nf][2]);
            accs[nf][3] = fmaf(mk1, L2E, accs[nf][3]);
        }

        // ---- online softmax (log2 domain) ----
        float tm0 = -INFINITY, tm1 = -INFINITY;
#pragma unroll
        for (int nf = 0; nf < 16; nf++) {
            tm0 = fmaxf(tm0, fmaxf(accs[nf][0], accs[nf][1]));
            tm1 = fmaxf(tm1, fmaxf(accs[nf][2], accs[nf][3]));
        }
        tm0 = fmaxf(tm0, __shfl_xor_sync(0xffffffffu, tm0, 1));
        tm0 = fmaxf(tm0, __shfl_xor_sync(0xffffffffu, tm0, 2));
        tm1 = fmaxf(tm1, __shfl_xor_sync(0xffffffffu, tm1, 1));
        tm1 = fmaxf(tm1, __shfl_xor_sync(0xffffffffu, tm1, 2));

        float mn0 = fmaxf(m0, tm0), mn1 = fmaxf(m1, tm1);
        float cr0 = ex2f(m0 - mn0), cr1 = ex2f(m1 - mn1);
        m0 = mn0; m1 = mn1;

        // ---- P = 2^(S-m) via packed fp16x2 exp ----
#pragma unroll
        for (int nf = 0; nf < 16; nf++) {
            pp[nf][0] = ex2h2(f2h2(accs[nf][0] - mn0, accs[nf][1] - mn0));
            pp[nf][1] = ex2h2(f2h2(accs[nf][2] - mn1, accs[nf][3] - mn1));
        }

#pragma unroll
        for (int nf = 0; nf < 8; nf++) {
            acco[nf][0] *= cr0; acco[nf][1] *= cr0;
            acco[nf][2] *= cr1; acco[nf][3] *= cr1;
        }
        acco_l[0] *= cr0;
        acco_l[2] *= cr1;

        // ---- O += P V ----
#pragma unroll
        for (int kc = 0; kc < 8; kc++) {
            uint32_t aph[4] = { pp[2 * kc][0], pp[2 * kc][1],
                                pp[2 * kc + 1][0], pp[2 * kc + 1][1] };
            mma_f16(acco_l, aph, bones);
#pragma unroll
            for (int pv = 0; pv < 4; pv++) {
                uint32_t vo = (uint32_t)((kc * 16 + rA) * ALDS + pv * 16 + cA) * 2;
                uint32_t h0, h1, h2, h3;
                ldmatrix_x4_trans(h0, h1, h2, h3, st + ABUF + vo);
                uint32_t bv0[2] = {h0, h1}, bv1[2] = {h2, h3};
                mma_f16(acco[2 * pv],     aph, bv0);
                mma_f16(acco[2 * pv + 1], aph, bv1);
            }
        }
    }

    // ---- epilogue: single-fp16 output ----
    float inv0 = 1.f / acco_l[0];
    float inv1 = 1.f / acco_l[2];
    int row0 = q0 + w * 16 + (lane >> 2);
#pragma unroll
    for (int nf = 0; nf < 8; nf++) {
        int d = nf * 8 + c0;
        size_t i0 = ((size_t)(b * NS) + row0) * NHID + h * DHEAD + d;
        size_t i1 = i0 + (size_t)8 * NHID;
        *(uint32_t*)(g_a16 + i0) = f2h2(acco[nf][0] * inv0, acco[nf][1] * inv0);
        *(uint32_t*)(g_a16 + i1) = f2h2(acco[nf][2] * inv1, acco[nf][3] * inv1);
    }
}

// ---------------------------------------------------------------------------
// Launch
// ---------------------------------------------------------------------------
extern "C" void kernel_launch(void* const* d_in, const int* in_sizes, int n_in,
                              void* d_out, int out_size)
{
    const float* X    = (const float*)d_in[0];
    const float* mask = (const float*)d_in[1];
    const float* Wq   = (const float*)d_in[2];
    const float* Wk   = (const float*)d_in[3];
    const float* Wv   = (const float*)d_in[4];
    const float* Wo   = (const float*)d_in[5];
    float* out = (float*)d_out;

    __half *x16, *w16, *wo16, *a16;
    cudaGetSymbolAddress((void**)&x16,  g_x16);
    cudaGetSymbolAddress((void**)&w16,  g_w16);
    cudaGetSymbolAddress((void**)&wo16, g_wo16);
    cudaGetSymbolAddress((void**)&a16,  g_a16);

    cudaFuncSetAttribute(gemm_1t_kernel,
                         cudaFuncAttributeMaxDynamicSharedMemorySize, GEMM_SMEM);
    cudaFuncSetAttribute(attn_tc_kernel,
                         cudaFuncAttributeMaxDynamicSharedMemorySize, ATTN_SMEM);

    int n4x = MTOT * NHID / 4;
    int n4w = NHID * NHID / 4;
    cvt_f16_kernel<<<n4x / 256, 256>>>(X, x16, n4x);
    cvt_f16_kernel<<<n4w / 256, 256>>>(Wq, w16,               n4w);
    cvt_f16_kernel<<<n4w / 256, 256>>>(Wk, w16 + NHID*NHID,   n4w);
    cvt_f16_kernel<<<n4w / 256, 256>>>(Wv, w16 + 2*NHID*NHID, n4w);
    cvt_f16_kernel<<<n4w / 256, 256>>>(Wo, wo16, n4w);

    // fused QKV GEMM (1-term)
    dim3 gq(3 * NHID / 256, MTOT / 128);   // 12 x 64
    gemm_1t_kernel<<<gq, 256, GEMM_SMEM>>>(x16, w16, nullptr, 1);

    // attention
    dim3 ga(NS / KT, NB * NHEADS);         // 16 x 64
    attn_tc_kernel<<<ga, 256, ATTN_SMEM>>>(mask);

    // output projection (1-term)
    dim3 go(NHID / 256, MTOT / 128);       // 4 x 64
    gemm_1t_kernel<<<go, 256, GEMM_SMEM>>>(a16, wo16, out, 0);
}